// round 12
// baseline (speedup 1.0000x reference)
#include <cuda_runtime.h>
#include <cuda_bf16.h>
#include <cstdint>

#define BATCH 16
#define SEQ   2048
#define DIM   512
typedef __nv_bfloat16 bf;

// ---------------------------------------------------------------------------
// Persistent scratch (device globals — allocation-free per harness rules)
// ---------------------------------------------------------------------------
__device__ bf    g_qinh[(size_t)BATCH * SEQ * DIM];   // query hi
__device__ bf    g_qinl[(size_t)BATCH * SEQ * DIM];   // query lo
__device__ bf    g_Winh[DIM * DIM];
__device__ bf    g_Winl[DIM * DIM];
__device__ bf    g_Wouth[DIM * 2 * DIM];
__device__ bf    g_Woutl[DIM * 2 * DIM];
__device__ bf    g_qh  [(size_t)BATCH * SEQ * DIM];   // q hi/lo
__device__ bf    g_ql  [(size_t)BATCH * SEQ * DIM];
__device__ bf    g_qTh [(size_t)BATCH * DIM * SEQ];   // q^T hi/lo
__device__ bf    g_qTl [(size_t)BATCH * DIM * SEQ];
__device__ bf    g_Wh  [(size_t)BATCH * SEQ * SEQ];   // softmax weights hi/lo
__device__ bf    g_Wl  [(size_t)BATCH * SEQ * SEQ];
__device__ bf    g_mixh[(size_t)BATCH * SEQ * DIM];
__device__ bf    g_mixl[(size_t)BATCH * SEQ * DIM];
__device__ float g_S   [(size_t)BATCH * SEQ * SEQ];   // fp32 scores

// ---------------------------------------------------------------------------
// PTX helpers (portable: ldmatrix / mma.sync / cp.async)
// ---------------------------------------------------------------------------
__device__ __forceinline__ uint32_t smem_u32(const void* p) {
    uint32_t a;
    asm("{ .reg .u64 t; cvta.to.shared.u64 t, %1; cvt.u32.u64 %0, t; }" : "=r"(a) : "l"(p));
    return a;
}
__device__ __forceinline__ void ldsm4(uint32_t* r, uint32_t addr) {
    asm volatile("ldmatrix.sync.aligned.m8n8.x4.shared.b16 {%0,%1,%2,%3}, [%4];"
                 : "=r"(r[0]), "=r"(r[1]), "=r"(r[2]), "=r"(r[3]) : "r"(addr));
}
__device__ __forceinline__ void mma16816(float* c, const uint32_t* a, const uint32_t* b) {
    asm volatile(
        "mma.sync.aligned.m16n8k16.row.col.f32.bf16.bf16.f32 "
        "{%0,%1,%2,%3}, {%4,%5,%6,%7}, {%8,%9}, {%0,%1,%2,%3};"
        : "+f"(c[0]), "+f"(c[1]), "+f"(c[2]), "+f"(c[3])
        : "r"(a[0]), "r"(a[1]), "r"(a[2]), "r"(a[3]), "r"(b[0]), "r"(b[1]));
}
#define CP16(s, g)  asm volatile("cp.async.cg.shared.global [%0], [%1], 16;" :: "r"(s), "l"(g) : "memory")
#define CP_COMMIT() asm volatile("cp.async.commit_group;" ::: "memory")
#define CP_WAIT0()  asm volatile("cp.async.wait_group 0;" ::: "memory")

__device__ __forceinline__ void split1(float v, bf& h, bf& l) {
    h = __float2bfloat16_rn(v);
    l = __float2bfloat16_rn(v - __bfloat162float(h));
}
__device__ __forceinline__ uint32_t pack2(bf a, bf b) {
    return ((uint32_t)__bfloat16_as_ushort(b) << 16) | __bfloat16_as_ushort(a);
}

// ---------------------------------------------------------------------------
// GEMM: C[128x128] = A @ B^T, bf16 hi/lo inputs, 3-term split, fp32 accum.
// All operands K-major bf16. K = nk*32. CONCAT: chunks>=16 read A1 (lda 512).
// EPI: 0 -> fp32 C, 1 -> bf16 hi/lo pair (Ch, Cl).
// 256 threads = 8 warps (4m x 2n), warp tile 32x64, mma m16n8k16.
// 2-stage cp.async pipeline, one __syncthreads per chunk, 2 CTA/SM.
// Warp phase-stagger: odd warps visit kk (and jh) in opposite order so LDSM
// bursts of half the warps overlap MMA bursts of the other half.
// ---------------------------------------------------------------------------
#define LDS 40  // bf16 per smem row (80B; 16B-aligned segments, conflict-free ldmatrix)
#define STG_BYTES (4 * 128 * LDS * 2)  // one stage: Ah,Al,Bh,Bl

template<int CONCAT, int EPI>
__device__ __forceinline__ void gemm_bf(
    const bf* __restrict__ Ah, const bf* __restrict__ Al,
    const bf* __restrict__ A1h, const bf* __restrict__ A1l, long lda,
    const bf* __restrict__ Bh, const bf* __restrict__ Bl, long ldb,
    int nk,
    float* __restrict__ C, bf* __restrict__ Ch, bf* __restrict__ Cl, long ldc,
    int m0, int n0)
{
    extern __shared__ bf sm[];
    const uint32_t uS = smem_u32(sm);

    const int tid = threadIdx.x;
    const int wid = tid >> 5, lane = tid & 31;
    const int wm = wid >> 1, wn = wid & 1;
    const int kkx = wid & 1;            // kk traversal stagger
    const int jhx = (wid >> 1) & 1;     // jh traversal stagger
    const int r = tid >> 1, h16 = (tid & 1) << 4;   // loader: row, 16-elem half

    const uint32_t rowoff = ((uint32_t)r * LDS + h16) * 2;

    auto issue = [&](int kc, int st) {
        const bf* a_h;
        const bf* a_l;
        if (CONCAT && kc >= 16) {
            a_h = A1h + (size_t)(m0 + r) * 512 + (size_t)(kc - 16) * 32 + h16;
            a_l = A1l + (size_t)(m0 + r) * 512 + (size_t)(kc - 16) * 32 + h16;
        } else {
            a_h = Ah + (size_t)(m0 + r) * lda + (size_t)kc * 32 + h16;
            a_l = Al + (size_t)(m0 + r) * lda + (size_t)kc * 32 + h16;
        }
        const bf* b_h = Bh + (size_t)(n0 + r) * ldb + (size_t)kc * 32 + h16;
        const bf* b_l = Bl + (size_t)(n0 + r) * ldb + (size_t)kc * 32 + h16;
        const uint32_t base = uS + (uint32_t)st * STG_BYTES + rowoff;
        CP16(base + 0 * 128 * LDS * 2,      a_h);
        CP16(base + 0 * 128 * LDS * 2 + 16, a_h + 8);
        CP16(base + 1 * 128 * LDS * 2,      a_l);
        CP16(base + 1 * 128 * LDS * 2 + 16, a_l + 8);
        CP16(base + 2 * 128 * LDS * 2,      b_h);
        CP16(base + 2 * 128 * LDS * 2 + 16, b_h + 8);
        CP16(base + 3 * 128 * LDS * 2,      b_l);
        CP16(base + 3 * 128 * LDS * 2 + 16, b_l + 8);
    };

    float acc[2][8][4] = {};

    issue(0, 0);
    CP_COMMIT();

    for (int kc = 0; kc < nk; ++kc) {
        const int st = kc & 1;
        CP_WAIT0();
        __syncthreads();
        if (kc + 1 < nk) { issue(kc + 1, st ^ 1); CP_COMMIT(); }

        const uint32_t sA  = uS + (uint32_t)st * STG_BYTES;
        const uint32_t sAl_ = sA + 128 * LDS * 2;
        const uint32_t sB  = sA + 2 * 128 * LDS * 2;
        const uint32_t sBl_ = sA + 3 * 128 * LDS * 2;

#pragma unroll
        for (int kk2 = 0; kk2 < 2; ++kk2) {
            const int kk = kk2 ^ kkx;
            const uint32_t aoff =
                ((uint32_t)(wm * 32 + (lane & 15)) * LDS + kk * 16 + ((lane & 16) ? 8 : 0)) * 2;
            uint32_t ah[2][4], al[2][4];
            ldsm4(ah[0], sA + aoff);
            ldsm4(ah[1], sA + aoff + 16 * LDS * 2);
            ldsm4(al[0], sAl_ + aoff);
            ldsm4(al[1], sAl_ + aoff + 16 * LDS * 2);

            const uint32_t boff =
                ((uint32_t)(wn * 64 + (lane & 7) + ((lane & 16) ? 8 : 0)) * LDS
                 + kk * 16 + ((lane & 8) ? 8 : 0)) * 2;

#pragma unroll
            for (int jh2 = 0; jh2 < 2; ++jh2) {
                const int jh = jh2 ^ jhx;
                uint32_t bh[4][2], bl[4][2];
#pragma unroll
                for (int jj = 0; jj < 2; ++jj) {
                    uint32_t tb[4], tl[4];
                    const uint32_t bo = boff + (jh * 2 + jj) * 16 * LDS * 2;
                    ldsm4(tb, sB + bo);
                    ldsm4(tl, sBl_ + bo);
                    bh[2 * jj][0] = tb[0]; bh[2 * jj][1] = tb[1];
                    bh[2 * jj + 1][0] = tb[2]; bh[2 * jj + 1][1] = tb[3];
                    bl[2 * jj][0] = tl[0]; bl[2 * jj][1] = tl[1];
                    bl[2 * jj + 1][0] = tl[2]; bl[2 * jj + 1][1] = tl[3];
                }
#pragma unroll
                for (int im = 0; im < 2; ++im)
#pragma unroll
                    for (int j = 0; j < 4; ++j)
                        mma16816(acc[im][jh * 4 + j], ah[im], bh[j]);
#pragma unroll
                for (int im = 0; im < 2; ++im)
#pragma unroll
                    for (int j = 0; j < 4; ++j)
                        mma16816(acc[im][jh * 4 + j], ah[im], bl[j]);
#pragma unroll
                for (int im = 0; im < 2; ++im)
#pragma unroll
                    for (int j = 0; j < 4; ++j)
                        mma16816(acc[im][jh * 4 + j], al[im], bh[j]);
            }
        }
    }

    // epilogue
    const int g = lane >> 2, tg = lane & 3;
#pragma unroll
    for (int im = 0; im < 2; ++im) {
        const size_t row = (size_t)(m0 + wm * 32 + im * 16 + g);
#pragma unroll
        for (int j = 0; j < 8; ++j) {
            const size_t col = (size_t)(n0 + wn * 64 + j * 8 + tg * 2);
            if (EPI == 0) {
                *(float2*)(C + row * ldc + col)       = make_float2(acc[im][j][0], acc[im][j][1]);
                *(float2*)(C + (row + 8) * ldc + col) = make_float2(acc[im][j][2], acc[im][j][3]);
            } else {
                bf h0, l0, h1, l1;
#pragma unroll
                for (int p = 0; p < 2; ++p) {
                    const size_t rr = (row + p * 8) * ldc + col;
                    split1(acc[im][j][2 * p],     h0, l0);
                    split1(acc[im][j][2 * p + 1], h1, l1);
                    *(uint32_t*)(Ch + rr) = pack2(h0, h1);
                    *(uint32_t*)(Cl + rr) = pack2(l0, l1);
                }
            }
        }
    }
}

// ---------------------------------------------------------------------------
// GEMM kernels
// ---------------------------------------------------------------------------
__global__ void __launch_bounds__(256, 2) k_qproj() {
    gemm_bf<0, 1>(g_qinh, g_qinl, nullptr, nullptr, DIM,
                  g_Winh, g_Winl, DIM, 16,
                  nullptr, g_qh, g_ql, DIM, blockIdx.y * 128, blockIdx.x * 128);
}
__global__ void __launch_bounds__(256, 2) k_scores() {
    if (blockIdx.x > blockIdx.y) return;   // fully masked causal tile
    const size_t qo = (size_t)blockIdx.z * SEQ * DIM;
    gemm_bf<0, 0>(g_qh + qo, g_ql + qo, nullptr, nullptr, DIM,
                  g_qh + qo, g_ql + qo, DIM, 16,
                  g_S + (size_t)blockIdx.z * SEQ * SEQ, nullptr, nullptr, SEQ,
                  blockIdx.y * 128, blockIdx.x * 128);
}
__global__ void __launch_bounds__(256, 2) k_mix() {
    // Longest-K tiles first: row tile 15 launches before row tile 0, so the
    // work-steal tail is filled by the short near-diagonal tiles.
    const int b = blockIdx.z;
    const int ry = (SEQ / 128 - 1) - blockIdx.y;
    const int m0 = ry * 128, n0 = blockIdx.x * 128;
    const size_t wo = (size_t)b * SEQ * SEQ, qo = (size_t)b * DIM * SEQ;
    const size_t mo = (size_t)b * SEQ * DIM;
    gemm_bf<0, 1>(g_Wh + wo, g_Wl + wo, nullptr, nullptr, SEQ,
                  g_qTh + qo, g_qTl + qo, SEQ, m0 / 32 + 4,
                  nullptr, g_mixh + mo, g_mixl + mo, DIM, m0, n0);
}
__global__ void __launch_bounds__(256, 2) k_out(float* __restrict__ out) {
    gemm_bf<1, 0>(g_mixh, g_mixl, g_qh, g_ql, DIM,
                  g_Wouth, g_Woutl, 2 * DIM, 32,
                  out, nullptr, nullptr, DIM, blockIdx.y * 128, blockIdx.x * 128);
}

// ---------------------------------------------------------------------------
// fp32 -> bf16 hi/lo split (pre-convert inputs)
// ---------------------------------------------------------------------------
__global__ void __launch_bounds__(256) k_cvt(const float* __restrict__ src,
                                             bf* __restrict__ dh, bf* __restrict__ dl,
                                             size_t n) {
    size_t i = ((size_t)blockIdx.x * 256 + threadIdx.x) * 4;
    if (i >= n) return;
    float4 v = *(const float4*)(src + i);
    bf h0, l0, h1, l1, h2, l2, h3, l3;
    split1(v.x, h0, l0); split1(v.y, h1, l1);
    split1(v.z, h2, l2); split1(v.w, h3, l3);
    *(uint2*)(dh + i) = make_uint2(pack2(h0, h1), pack2(h2, h3));
    *(uint2*)(dl + i) = make_uint2(pack2(l0, l1), pack2(l2, l3));
}

// ---------------------------------------------------------------------------
// Transpose bf16 hi/lo: qT[b][d][n] = q[b][n][d]
// ---------------------------------------------------------------------------
__global__ void __launch_bounds__(256) k_transpose() {
    __shared__ bf th[32][33];
    __shared__ bf tl[32][33];
    const int b = blockIdx.z, n0 = blockIdx.x * 32, d0 = blockIdx.y * 32;
    const int tx = threadIdx.x & 31, ty = threadIdx.x >> 5;
    const size_t so = (size_t)b * SEQ * DIM, to = (size_t)b * DIM * SEQ;
#pragma unroll
    for (int j = 0; j < 4; ++j) {
        const size_t idx = so + (size_t)(n0 + ty + 8 * j) * DIM + d0 + tx;
        th[ty + 8 * j][tx] = g_qh[idx];
        tl[ty + 8 * j][tx] = g_ql[idx];
    }
    __syncthreads();
#pragma unroll
    for (int j = 0; j < 4; ++j) {
        const size_t idx = to + (size_t)(d0 + ty + 8 * j) * SEQ + n0 + tx;
        g_qTh[idx] = th[tx][ty + 8 * j];
        g_qTl[idx] = tl[tx][ty + 8 * j];
    }
}

// ---------------------------------------------------------------------------
// Softmax: row n over keys m < n (strict causal); emits bf16 hi/lo weights.
// Thread t owns 8 contiguous elements [t*8, t*8+8): 2x float4 load,
// 1x uint4 store per hi/lo. Writes only up to the 128-aligned k_mix limit.
// ---------------------------------------------------------------------------
__global__ void __launch_bounds__(256) k_softmax() {
    const int n = blockIdx.x, b = blockIdx.y;
    const size_t ro = ((size_t)b * SEQ + n) * SEQ;
    const float* row = g_S + ro;
    bf* wh = g_Wh + ro;
    bf* wl = g_Wl + ro;
    const int tid = threadIdx.x;
    const int mb = tid * 8;                   // my 8-element base
    const int lim = (n / 128) * 128 + 128;    // k_mix never reads beyond this
    __shared__ float red[8];

    float f[8];
    if (n > 0 && mb < n) {
        float4 v0 = *(const float4*)(row + mb);
        float4 v1 = *(const float4*)(row + mb + 4);
        f[0] = v0.x; f[1] = v0.y; f[2] = v0.z; f[3] = v0.w;
        f[4] = v1.x; f[5] = v1.y; f[6] = v1.z; f[7] = v1.w;
#pragma unroll
        for (int i = 0; i < 8; ++i)
            if (mb + i >= n) f[i] = -3.0e38f;
    } else {
#pragma unroll
        for (int i = 0; i < 8; ++i) f[i] = -3.0e38f;
    }

    if (n > 0) {
        float mx = -3.0e38f;
#pragma unroll
        for (int i = 0; i < 8; ++i) mx = fmaxf(mx, f[i]);
#pragma unroll
        for (int o = 16; o > 0; o >>= 1) mx = fmaxf(mx, __shfl_xor_sync(0xffffffffu, mx, o));
        if ((tid & 31) == 0) red[tid >> 5] = mx;
        __syncthreads();
        float bmx = red[0];
#pragma unroll
        for (int w = 1; w < 8; ++w) bmx = fmaxf(bmx, red[w]);
        __syncthreads();
        float s = 0.f;
#pragma unroll
        for (int i = 0; i < 8; ++i) {
            f[i] = (mb + i < n) ? __expf(f[i] - bmx) : 0.f;
            s += f[i];
        }
#pragma unroll
        for (int o = 16; o > 0; o >>= 1) s += __shfl_xor_sync(0xffffffffu, s, o);
        if ((tid & 31) == 0) red[tid >> 5] = s;
        __syncthreads();
        float tot = 0.f;
#pragma unroll
        for (int w = 0; w < 8; ++w) tot += red[w];
        const float inv = 1.f / tot;
#pragma unroll
        for (int i = 0; i < 8; ++i) f[i] *= inv;
    } else {
#pragma unroll
        for (int i = 0; i < 8; ++i) f[i] = 0.f;
    }

    if (mb < lim) {   // lim is a multiple of 8: whole group in or out
        bf h[8], l[8];
#pragma unroll
        for (int i = 0; i < 8; ++i) split1(f[i], h[i], l[i]);
        *(uint4*)(wh + mb) = make_uint4(pack2(h[0], h[1]), pack2(h[2], h[3]),
                                        pack2(h[4], h[5]), pack2(h[6], h[7]));
        *(uint4*)(wl + mb) = make_uint4(pack2(l[0], l[1]), pack2(l[2], l[3]),
                                        pack2(l[4], l[5]), pack2(l[6], l[7]));
    }
}

// ---------------------------------------------------------------------------
extern "C" void kernel_launch(void* const* d_in, const int* in_sizes, int n_in,
                              void* d_out, int out_size) {
    const float* query = (const float*)d_in[0];   // [16, 2048, 512]
    const float* W_in  = (const float*)d_in[1];   // [512, 512]
    const float* W_out = (const float*)d_in[2];   // [512, 1024]
    float* out = (float*)d_out;                   // [16, 2048, 512]

    const int smem = 2 * STG_BYTES;  // 81920
    static int init = 0;
    if (!init) {
        cudaFuncSetAttribute(k_qproj,  cudaFuncAttributeMaxDynamicSharedMemorySize, smem);
        cudaFuncSetAttribute(k_scores, cudaFuncAttributeMaxDynamicSharedMemorySize, smem);
        cudaFuncSetAttribute(k_mix,    cudaFuncAttributeMaxDynamicSharedMemorySize, smem);
        cudaFuncSetAttribute(k_out,    cudaFuncAttributeMaxDynamicSharedMemorySize, smem);
        init = 1;
    }

    bf *qinh, *qinl, *winh, *winl, *wouth, *woutl;
    cudaGetSymbolAddress((void**)&qinh,  g_qinh);
    cudaGetSymbolAddress((void**)&qinl,  g_qinl);
    cudaGetSymbolAddress((void**)&winh,  g_Winh);
    cudaGetSymbolAddress((void**)&winl,  g_Winl);
    cudaGetSymbolAddress((void**)&wouth, g_Wouth);
    cudaGetSymbolAddress((void**)&woutl, g_Woutl);

    const size_t nq = (size_t)BATCH * SEQ * DIM;
    k_cvt<<<(unsigned)((nq / 4 + 255) / 256), 256>>>(query, qinh, qinl, nq);
    k_cvt<<<(DIM * DIM / 4 + 255) / 256, 256>>>(W_in, winh, winl, DIM * DIM);
    k_cvt<<<(DIM * 2 * DIM / 4 + 255) / 256, 256>>>(W_out, wouth, woutl, DIM * 2 * DIM);

    k_qproj    <<<dim3(DIM / 128, (BATCH * SEQ) / 128), 256, smem>>>();
    k_transpose<<<dim3(SEQ / 32, DIM / 32, BATCH),      256>>>();
    k_scores   <<<dim3(SEQ / 128, SEQ / 128, BATCH),    256, smem>>>();
    k_softmax  <<<dim3(SEQ, BATCH),                     256>>>();
    k_mix      <<<dim3(DIM / 128, SEQ / 128, BATCH),    256, smem>>>();
    k_out      <<<dim3(DIM / 128, (BATCH * SEQ) / 128), 256, smem>>>(out);
}

// round 13
// speedup vs baseline: 2.2743x; 2.2743x over previous
#include <cuda_runtime.h>
#include <cuda_bf16.h>
#include <cstdint>

#define BATCH 16
#define SEQ   2048
#define DIM   512
typedef __nv_bfloat16 bf;

// ---------------------------------------------------------------------------
// Persistent scratch (device globals — allocation-free per harness rules)
// ---------------------------------------------------------------------------
__device__ bf    g_qinh[(size_t)BATCH * SEQ * DIM];   // query hi
__device__ bf    g_qinl[(size_t)BATCH * SEQ * DIM];   // query lo
__device__ bf    g_Winh[DIM * DIM];
__device__ bf    g_Winl[DIM * DIM];
__device__ bf    g_Wouth[DIM * 2 * DIM];
__device__ bf    g_Woutl[DIM * 2 * DIM];
__device__ bf    g_qh  [(size_t)BATCH * SEQ * DIM];   // q hi/lo
__device__ bf    g_ql  [(size_t)BATCH * SEQ * DIM];
__device__ bf    g_qTh [(size_t)BATCH * DIM * SEQ];   // q^T hi/lo
__device__ bf    g_qTl [(size_t)BATCH * DIM * SEQ];
__device__ bf    g_Wh  [(size_t)BATCH * SEQ * SEQ];   // softmax weights hi/lo
__device__ bf    g_Wl  [(size_t)BATCH * SEQ * SEQ];
__device__ bf    g_mixh[(size_t)BATCH * SEQ * DIM];
__device__ bf    g_mixl[(size_t)BATCH * SEQ * DIM];
__device__ float g_S   [(size_t)BATCH * SEQ * SEQ];   // fp32 scores

// ---------------------------------------------------------------------------
// PTX helpers (portable: ldmatrix / mma.sync / cp.async)
// ---------------------------------------------------------------------------
__device__ __forceinline__ uint32_t smem_u32(const void* p) {
    uint32_t a;
    asm("{ .reg .u64 t; cvta.to.shared.u64 t, %1; cvt.u32.u64 %0, t; }" : "=r"(a) : "l"(p));
    return a;
}
__device__ __forceinline__ void ldsm4(uint32_t* r, uint32_t addr) {
    asm volatile("ldmatrix.sync.aligned.m8n8.x4.shared.b16 {%0,%1,%2,%3}, [%4];"
                 : "=r"(r[0]), "=r"(r[1]), "=r"(r[2]), "=r"(r[3]) : "r"(addr));
}
__device__ __forceinline__ void mma16816(float* c, const uint32_t* a, const uint32_t* b) {
    asm volatile(
        "mma.sync.aligned.m16n8k16.row.col.f32.bf16.bf16.f32 "
        "{%0,%1,%2,%3}, {%4,%5,%6,%7}, {%8,%9}, {%0,%1,%2,%3};"
        : "+f"(c[0]), "+f"(c[1]), "+f"(c[2]), "+f"(c[3])
        : "r"(a[0]), "r"(a[1]), "r"(a[2]), "r"(a[3]), "r"(b[0]), "r"(b[1]));
}
#define CP16(s, g)  asm volatile("cp.async.cg.shared.global [%0], [%1], 16;" :: "r"(s), "l"(g) : "memory")
#define CP_COMMIT() asm volatile("cp.async.commit_group;" ::: "memory")
#define CP_WAIT0()  asm volatile("cp.async.wait_group 0;" ::: "memory")

__device__ __forceinline__ void split1(float v, bf& h, bf& l) {
    h = __float2bfloat16_rn(v);
    l = __float2bfloat16_rn(v - __bfloat162float(h));
}
__device__ __forceinline__ uint32_t pack2(bf a, bf b) {
    return ((uint32_t)__bfloat16_as_ushort(b) << 16) | __bfloat16_as_ushort(a);
}

// ---------------------------------------------------------------------------
// GEMM: C[128x128] = A @ B^T, bf16 hi/lo inputs, 3-term split, fp32 accum.
// All operands K-major bf16. K = nk*32. CONCAT: chunks>=16 read A1 (lda 512).
// EPI: 0 -> fp32 C, 1 -> bf16 hi/lo pair (Ch, Cl).
// 256 threads = 8 warps (4m x 2n), warp tile 32x64, mma m16n8k16.
// 2-stage cp.async pipeline, one __syncthreads per chunk, 2 CTA/SM.
// kk-stagger only (address-level; acc indices stay compile-time constant —
// R12 showed runtime acc indices demote the accumulators to local memory).
// ---------------------------------------------------------------------------
#define LDS 40  // bf16 per smem row (80B; 16B-aligned segments, conflict-free ldmatrix)
#define STG_BYTES (4 * 128 * LDS * 2)  // one stage: Ah,Al,Bh,Bl

template<int CONCAT, int EPI>
__device__ __forceinline__ void gemm_bf(
    const bf* __restrict__ Ah, const bf* __restrict__ Al,
    const bf* __restrict__ A1h, const bf* __restrict__ A1l, long lda,
    const bf* __restrict__ Bh, const bf* __restrict__ Bl, long ldb,
    int nk,
    float* __restrict__ C, bf* __restrict__ Ch, bf* __restrict__ Cl, long ldc,
    int m0, int n0)
{
    extern __shared__ bf sm[];
    const uint32_t uS = smem_u32(sm);

    const int tid = threadIdx.x;
    const int wid = tid >> 5, lane = tid & 31;
    const int wm = wid >> 1, wn = wid & 1;
    const int kkx = wid & 1;            // kk traversal stagger (addresses only)
    const int r = tid >> 1, h16 = (tid & 1) << 4;   // loader: row, 16-elem half

    const uint32_t rowoff = ((uint32_t)r * LDS + h16) * 2;

    auto issue = [&](int kc, int st) {
        const bf* a_h;
        const bf* a_l;
        if (CONCAT && kc >= 16) {
            a_h = A1h + (size_t)(m0 + r) * 512 + (size_t)(kc - 16) * 32 + h16;
            a_l = A1l + (size_t)(m0 + r) * 512 + (size_t)(kc - 16) * 32 + h16;
        } else {
            a_h = Ah + (size_t)(m0 + r) * lda + (size_t)kc * 32 + h16;
            a_l = Al + (size_t)(m0 + r) * lda + (size_t)kc * 32 + h16;
        }
        const bf* b_h = Bh + (size_t)(n0 + r) * ldb + (size_t)kc * 32 + h16;
        const bf* b_l = Bl + (size_t)(n0 + r) * ldb + (size_t)kc * 32 + h16;
        const uint32_t base = uS + (uint32_t)st * STG_BYTES + rowoff;
        CP16(base + 0 * 128 * LDS * 2,      a_h);
        CP16(base + 0 * 128 * LDS * 2 + 16, a_h + 8);
        CP16(base + 1 * 128 * LDS * 2,      a_l);
        CP16(base + 1 * 128 * LDS * 2 + 16, a_l + 8);
        CP16(base + 2 * 128 * LDS * 2,      b_h);
        CP16(base + 2 * 128 * LDS * 2 + 16, b_h + 8);
        CP16(base + 3 * 128 * LDS * 2,      b_l);
        CP16(base + 3 * 128 * LDS * 2 + 16, b_l + 8);
    };

    float acc[2][8][4] = {};

    issue(0, 0);
    CP_COMMIT();

    for (int kc = 0; kc < nk; ++kc) {
        const int st = kc & 1;
        CP_WAIT0();
        __syncthreads();
        if (kc + 1 < nk) { issue(kc + 1, st ^ 1); CP_COMMIT(); }

        const uint32_t sA  = uS + (uint32_t)st * STG_BYTES;
        const uint32_t sAl_ = sA + 128 * LDS * 2;
        const uint32_t sB  = sA + 2 * 128 * LDS * 2;
        const uint32_t sBl_ = sA + 3 * 128 * LDS * 2;

#pragma unroll
        for (int kk2 = 0; kk2 < 2; ++kk2) {
            const int kk = kk2 ^ kkx;   // address-level only; acc indices const
            const uint32_t aoff =
                ((uint32_t)(wm * 32 + (lane & 15)) * LDS + kk * 16 + ((lane & 16) ? 8 : 0)) * 2;
            uint32_t ah[2][4], al[2][4];
            ldsm4(ah[0], sA + aoff);
            ldsm4(ah[1], sA + aoff + 16 * LDS * 2);
            ldsm4(al[0], sAl_ + aoff);
            ldsm4(al[1], sAl_ + aoff + 16 * LDS * 2);

            const uint32_t boff =
                ((uint32_t)(wn * 64 + (lane & 7) + ((lane & 16) ? 8 : 0)) * LDS
                 + kk * 16 + ((lane & 8) ? 8 : 0)) * 2;

#pragma unroll
            for (int jh = 0; jh < 2; ++jh) {
                uint32_t bh[4][2], bl[4][2];
#pragma unroll
                for (int jj = 0; jj < 2; ++jj) {
                    uint32_t tb[4], tl[4];
                    const uint32_t bo = boff + (jh * 2 + jj) * 16 * LDS * 2;
                    ldsm4(tb, sB + bo);
                    ldsm4(tl, sBl_ + bo);
                    bh[2 * jj][0] = tb[0]; bh[2 * jj][1] = tb[1];
                    bh[2 * jj + 1][0] = tb[2]; bh[2 * jj + 1][1] = tb[3];
                    bl[2 * jj][0] = tl[0]; bl[2 * jj][1] = tl[1];
                    bl[2 * jj + 1][0] = tl[2]; bl[2 * jj + 1][1] = tl[3];
                }
#pragma unroll
                for (int im = 0; im < 2; ++im)
#pragma unroll
                    for (int j = 0; j < 4; ++j)
                        mma16816(acc[im][jh * 4 + j], ah[im], bh[j]);
#pragma unroll
                for (int im = 0; im < 2; ++im)
#pragma unroll
                    for (int j = 0; j < 4; ++j)
                        mma16816(acc[im][jh * 4 + j], ah[im], bl[j]);
#pragma unroll
                for (int im = 0; im < 2; ++im)
#pragma unroll
                    for (int j = 0; j < 4; ++j)
                        mma16816(acc[im][jh * 4 + j], al[im], bh[j]);
            }
        }
    }

    // epilogue
    const int g = lane >> 2, tg = lane & 3;
#pragma unroll
    for (int im = 0; im < 2; ++im) {
        const size_t row = (size_t)(m0 + wm * 32 + im * 16 + g);
#pragma unroll
        for (int j = 0; j < 8; ++j) {
            const size_t col = (size_t)(n0 + wn * 64 + j * 8 + tg * 2);
            if (EPI == 0) {
                *(float2*)(C + row * ldc + col)       = make_float2(acc[im][j][0], acc[im][j][1]);
                *(float2*)(C + (row + 8) * ldc + col) = make_float2(acc[im][j][2], acc[im][j][3]);
            } else {
                bf h0, l0, h1, l1;
#pragma unroll
                for (int p = 0; p < 2; ++p) {
                    const size_t rr = (row + p * 8) * ldc + col;
                    split1(acc[im][j][2 * p],     h0, l0);
                    split1(acc[im][j][2 * p + 1], h1, l1);
                    *(uint32_t*)(Ch + rr) = pack2(h0, h1);
                    *(uint32_t*)(Cl + rr) = pack2(l0, l1);
                }
            }
        }
    }
}

// ---------------------------------------------------------------------------
// GEMM kernels
// ---------------------------------------------------------------------------
__global__ void __launch_bounds__(256, 2) k_qproj() {
    gemm_bf<0, 1>(g_qinh, g_qinl, nullptr, nullptr, DIM,
                  g_Winh, g_Winl, DIM, 16,
                  nullptr, g_qh, g_ql, DIM, blockIdx.y * 128, blockIdx.x * 128);
}
__global__ void __launch_bounds__(256, 2) k_scores() {
    if (blockIdx.x > blockIdx.y) return;   // fully masked causal tile
    const size_t qo = (size_t)blockIdx.z * SEQ * DIM;
    gemm_bf<0, 0>(g_qh + qo, g_ql + qo, nullptr, nullptr, DIM,
                  g_qh + qo, g_ql + qo, DIM, 16,
                  g_S + (size_t)blockIdx.z * SEQ * SEQ, nullptr, nullptr, SEQ,
                  blockIdx.y * 128, blockIdx.x * 128);
}
__global__ void __launch_bounds__(256, 2) k_mix() {
    // Longest-K tiles first: row tile 15 launches before row tile 0, so the
    // work-steal tail is filled by the short near-diagonal tiles.
    const int b = blockIdx.z;
    const int ry = (SEQ / 128 - 1) - blockIdx.y;
    const int m0 = ry * 128, n0 = blockIdx.x * 128;
    const size_t wo = (size_t)b * SEQ * SEQ, qo = (size_t)b * DIM * SEQ;
    const size_t mo = (size_t)b * SEQ * DIM;
    gemm_bf<0, 1>(g_Wh + wo, g_Wl + wo, nullptr, nullptr, SEQ,
                  g_qTh + qo, g_qTl + qo, SEQ, m0 / 32 + 4,
                  nullptr, g_mixh + mo, g_mixl + mo, DIM, m0, n0);
}
__global__ void __launch_bounds__(256, 2) k_out(float* __restrict__ out) {
    gemm_bf<1, 0>(g_mixh, g_mixl, g_qh, g_ql, DIM,
                  g_Wouth, g_Woutl, 2 * DIM, 32,
                  out, nullptr, nullptr, DIM, blockIdx.y * 128, blockIdx.x * 128);
}

// ---------------------------------------------------------------------------
// fp32 -> bf16 hi/lo split (pre-convert inputs)
// ---------------------------------------------------------------------------
__global__ void __launch_bounds__(256) k_cvt(const float* __restrict__ src,
                                             bf* __restrict__ dh, bf* __restrict__ dl,
                                             size_t n) {
    size_t i = ((size_t)blockIdx.x * 256 + threadIdx.x) * 4;
    if (i >= n) return;
    float4 v = *(const float4*)(src + i);
    bf h0, l0, h1, l1, h2, l2, h3, l3;
    split1(v.x, h0, l0); split1(v.y, h1, l1);
    split1(v.z, h2, l2); split1(v.w, h3, l3);
    *(uint2*)(dh + i) = make_uint2(pack2(h0, h1), pack2(h2, h3));
    *(uint2*)(dl + i) = make_uint2(pack2(l0, l1), pack2(l2, l3));
}

// ---------------------------------------------------------------------------
// Transpose bf16 hi/lo: qT[b][d][n] = q[b][n][d]
// ---------------------------------------------------------------------------
__global__ void __launch_bounds__(256) k_transpose() {
    __shared__ bf th[32][33];
    __shared__ bf tl[32][33];
    const int b = blockIdx.z, n0 = blockIdx.x * 32, d0 = blockIdx.y * 32;
    const int tx = threadIdx.x & 31, ty = threadIdx.x >> 5;
    const size_t so = (size_t)b * SEQ * DIM, to = (size_t)b * DIM * SEQ;
#pragma unroll
    for (int j = 0; j < 4; ++j) {
        const size_t idx = so + (size_t)(n0 + ty + 8 * j) * DIM + d0 + tx;
        th[ty + 8 * j][tx] = g_qh[idx];
        tl[ty + 8 * j][tx] = g_ql[idx];
    }
    __syncthreads();
#pragma unroll
    for (int j = 0; j < 4; ++j) {
        const size_t idx = to + (size_t)(d0 + ty + 8 * j) * SEQ + n0 + tx;
        g_qTh[idx] = th[tx][ty + 8 * j];
        g_qTl[idx] = tl[tx][ty + 8 * j];
    }
}

// ---------------------------------------------------------------------------
// Softmax: row n over keys m < n (strict causal); emits bf16 hi/lo weights.
// Thread t owns 8 contiguous elements: 2x float4 load, uint4 stores.
// Writes only up to the 128-aligned k_mix limit.
// ---------------------------------------------------------------------------
__global__ void __launch_bounds__(256) k_softmax() {
    const int n = blockIdx.x, b = blockIdx.y;
    const size_t ro = ((size_t)b * SEQ + n) * SEQ;
    const float* row = g_S + ro;
    bf* wh = g_Wh + ro;
    bf* wl = g_Wl + ro;
    const int tid = threadIdx.x;
    const int mb = tid * 8;                   // my 8-element base
    const int lim = (n / 128) * 128 + 128;    // k_mix never reads beyond this
    __shared__ float red[8];

    float f[8];
    if (n > 0 && mb < n) {
        float4 v0 = *(const float4*)(row + mb);
        float4 v1 = *(const float4*)(row + mb + 4);
        f[0] = v0.x; f[1] = v0.y; f[2] = v0.z; f[3] = v0.w;
        f[4] = v1.x; f[5] = v1.y; f[6] = v1.z; f[7] = v1.w;
#pragma unroll
        for (int i = 0; i < 8; ++i)
            if (mb + i >= n) f[i] = -3.0e38f;
    } else {
#pragma unroll
        for (int i = 0; i < 8; ++i) f[i] = -3.0e38f;
    }

    if (n > 0) {
        float mx = -3.0e38f;
#pragma unroll
        for (int i = 0; i < 8; ++i) mx = fmaxf(mx, f[i]);
#pragma unroll
        for (int o = 16; o > 0; o >>= 1) mx = fmaxf(mx, __shfl_xor_sync(0xffffffffu, mx, o));
        if ((tid & 31) == 0) red[tid >> 5] = mx;
        __syncthreads();
        float bmx = red[0];
#pragma unroll
        for (int w = 1; w < 8; ++w) bmx = fmaxf(bmx, red[w]);
        __syncthreads();
        float s = 0.f;
#pragma unroll
        for (int i = 0; i < 8; ++i) {
            f[i] = (mb + i < n) ? __expf(f[i] - bmx) : 0.f;
            s += f[i];
        }
#pragma unroll
        for (int o = 16; o > 0; o >>= 1) s += __shfl_xor_sync(0xffffffffu, s, o);
        if ((tid & 31) == 0) red[tid >> 5] = s;
        __syncthreads();
        float tot = 0.f;
#pragma unroll
        for (int w = 0; w < 8; ++w) tot += red[w];
        const float inv = 1.f / tot;
#pragma unroll
        for (int i = 0; i < 8; ++i) f[i] *= inv;
    } else {
#pragma unroll
        for (int i = 0; i < 8; ++i) f[i] = 0.f;
    }

    if (mb < lim) {   // lim is a multiple of 8: whole group in or out
        bf h[8], l[8];
#pragma unroll
        for (int i = 0; i < 8; ++i) split1(f[i], h[i], l[i]);
        *(uint4*)(wh + mb) = make_uint4(pack2(h[0], h[1]), pack2(h[2], h[3]),
                                        pack2(h[4], h[5]), pack2(h[6], h[7]));
        *(uint4*)(wl + mb) = make_uint4(pack2(l[0], l[1]), pack2(l[2], l[3]),
                                        pack2(l[4], l[5]), pack2(l[6], l[7]));
    }
}

// ---------------------------------------------------------------------------
extern "C" void kernel_launch(void* const* d_in, const int* in_sizes, int n_in,
                              void* d_out, int out_size) {
    const float* query = (const float*)d_in[0];   // [16, 2048, 512]
    const float* W_in  = (const float*)d_in[1];   // [512, 512]
    const float* W_out = (const float*)d_in[2];   // [512, 1024]
    float* out = (float*)d_out;                   // [16, 2048, 512]

    const int smem = 2 * STG_BYTES;  // 81920
    static int init = 0;
    if (!init) {
        cudaFuncSetAttribute(k_qproj,  cudaFuncAttributeMaxDynamicSharedMemorySize, smem);
        cudaFuncSetAttribute(k_scores, cudaFuncAttributeMaxDynamicSharedMemorySize, smem);
        cudaFuncSetAttribute(k_mix,    cudaFuncAttributeMaxDynamicSharedMemorySize, smem);
        cudaFuncSetAttribute(k_out,    cudaFuncAttributeMaxDynamicSharedMemorySize, smem);
        init = 1;
    }

    bf *qinh, *qinl, *winh, *winl, *wouth, *woutl;
    cudaGetSymbolAddress((void**)&qinh,  g_qinh);
    cudaGetSymbolAddress((void**)&qinl,  g_qinl);
    cudaGetSymbolAddress((void**)&winh,  g_Winh);
    cudaGetSymbolAddress((void**)&winl,  g_Winl);
    cudaGetSymbolAddress((void**)&wouth, g_Wouth);
    cudaGetSymbolAddress((void**)&woutl, g_Woutl);

    const size_t nq = (size_t)BATCH * SEQ * DIM;
    k_cvt<<<(unsigned)((nq / 4 + 255) / 256), 256>>>(query, qinh, qinl, nq);
    k_cvt<<<(DIM * DIM / 4 + 255) / 256, 256>>>(W_in, winh, winl, DIM * DIM);
    k_cvt<<<(DIM * 2 * DIM / 4 + 255) / 256, 256>>>(W_out, wouth, woutl, DIM * 2 * DIM);

    k_qproj    <<<dim3(DIM / 128, (BATCH * SEQ) / 128), 256, smem>>>();
    k_transpose<<<dim3(SEQ / 32, DIM / 32, BATCH),      256>>>();
    k_scores   <<<dim3(SEQ / 128, SEQ / 128, BATCH),    256, smem>>>();
    k_softmax  <<<dim3(SEQ, BATCH),                     256>>>();
    k_mix      <<<dim3(DIM / 128, SEQ / 128, BATCH),    256, smem>>>();
    k_out      <<<dim3(DIM / 128, (BATCH * SEQ) / 128), 256, smem>>>(out);
}

// round 14
// speedup vs baseline: 2.6836x; 1.1800x over previous
#include <cuda_runtime.h>
#include <cuda_bf16.h>
#include <cuda_fp16.h>
#include <cstdint>

#define BATCH 16
#define SEQ   2048
#define DIM   512
typedef __nv_bfloat16 bf;

// ---------------------------------------------------------------------------
// Persistent scratch (device globals — allocation-free per harness rules)
// ---------------------------------------------------------------------------
__device__ bf     g_qinh[(size_t)BATCH * SEQ * DIM];   // query bf16 hi/lo
__device__ bf     g_qinl[(size_t)BATCH * SEQ * DIM];
__device__ bf     g_Winh[DIM * DIM];
__device__ bf     g_Winl[DIM * DIM];
__device__ __half g_Wo16h[DIM * 2 * DIM];              // W_out fp16 hi/lo
__device__ __half g_Wo16l[DIM * 2 * DIM];
__device__ bf     g_qh  [(size_t)BATCH * SEQ * DIM];   // q bf16 hi/lo (scores)
__device__ bf     g_ql  [(size_t)BATCH * SEQ * DIM];
__device__ __half g_qfh [(size_t)BATCH * SEQ * DIM];   // q fp16 hi (k_out A)
__device__ __half g_qT16h[(size_t)BATCH * DIM * SEQ];  // q^T fp16 hi/lo (mix B)
__device__ __half g_qT16l[(size_t)BATCH * DIM * SEQ];
__device__ __half g_Wfh [(size_t)BATCH * SEQ * SEQ];   // softmax weights fp16 hi
__device__ __half g_mixfh[(size_t)BATCH * SEQ * DIM];  // mix fp16 hi
__device__ float  g_S   [(size_t)BATCH * SEQ * SEQ];   // fp32 scores

// ---------------------------------------------------------------------------
// PTX helpers (portable: ldmatrix / mma.sync / cp.async)
// ---------------------------------------------------------------------------
__device__ __forceinline__ uint32_t smem_u32(const void* p) {
    uint32_t a;
    asm("{ .reg .u64 t; cvta.to.shared.u64 t, %1; cvt.u32.u64 %0, t; }" : "=r"(a) : "l"(p));
    return a;
}
__device__ __forceinline__ void ldsm4(uint32_t* r, uint32_t addr) {
    asm volatile("ldmatrix.sync.aligned.m8n8.x4.shared.b16 {%0,%1,%2,%3}, [%4];"
                 : "=r"(r[0]), "=r"(r[1]), "=r"(r[2]), "=r"(r[3]) : "r"(addr));
}
__device__ __forceinline__ void mma_bf16(float* c, const uint32_t* a, const uint32_t* b) {
    asm volatile(
        "mma.sync.aligned.m16n8k16.row.col.f32.bf16.bf16.f32 "
        "{%0,%1,%2,%3}, {%4,%5,%6,%7}, {%8,%9}, {%0,%1,%2,%3};"
        : "+f"(c[0]), "+f"(c[1]), "+f"(c[2]), "+f"(c[3])
        : "r"(a[0]), "r"(a[1]), "r"(a[2]), "r"(a[3]), "r"(b[0]), "r"(b[1]));
}
__device__ __forceinline__ void mma_f16(float* c, const uint32_t* a, const uint32_t* b) {
    asm volatile(
        "mma.sync.aligned.m16n8k16.row.col.f32.f16.f16.f32 "
        "{%0,%1,%2,%3}, {%4,%5,%6,%7}, {%8,%9}, {%0,%1,%2,%3};"
        : "+f"(c[0]), "+f"(c[1]), "+f"(c[2]), "+f"(c[3])
        : "r"(a[0]), "r"(a[1]), "r"(a[2]), "r"(a[3]), "r"(b[0]), "r"(b[1]));
}
#define CP16(s, g)  asm volatile("cp.async.cg.shared.global [%0], [%1], 16;" :: "r"(s), "l"(g) : "memory")
#define CP_COMMIT() asm volatile("cp.async.commit_group;" ::: "memory")
#define CP_WAIT0()  asm volatile("cp.async.wait_group 0;" ::: "memory")

__device__ __forceinline__ void split1(float v, bf& h, bf& l) {
    h = __float2bfloat16_rn(v);
    l = __float2bfloat16_rn(v - __bfloat162float(h));
}
__device__ __forceinline__ uint32_t pack2(bf a, bf b) {
    return ((uint32_t)__bfloat16_as_ushort(b) << 16) | __bfloat16_as_ushort(a);
}
__device__ __forceinline__ uint32_t pack2h(__half a, __half b) {
    return ((uint32_t)__half_as_ushort(b) << 16) | __half_as_ushort(a);
}

// ---------------------------------------------------------------------------
// GEMM: C[128x128] = A @ B^T, fp32 accum, m16n8k16 mma.
// F16=0: bf16 3-pass split (hh + ah*bl + al*bh) — qproj, scores.
// F16=1: fp16 2-pass split (hh + ah*bl), A hi only — mix, out.
// Operands K-major 16-bit. K = nk*32. CONCAT: chunks>=16 read A1 (lda 512).
// EPI: 0 -> fp32 C; 1 -> bf16 (Ch,Cl) + fp16 Cf; 2 -> fp16 Cf only.
// 256 threads = 8 warps (4m x 2n), warp tile 32x64, 2-stage cp.async,
// one __syncthreads per chunk, 2 CTA/SM. Acc indices compile-time constant.
// ---------------------------------------------------------------------------
#define LDS 40  // 16-bit elems per smem row (80B; conflict-free ldmatrix)
#define STG_BYTES (4 * 128 * LDS * 2)  // one stage: Ah,Al,Bh,Bl regions

template<int CONCAT, int EPI, int F16>
__device__ __forceinline__ void gemm_core(
    const uint16_t* __restrict__ Ah, const uint16_t* __restrict__ Al,
    const uint16_t* __restrict__ A1h, long lda,
    const uint16_t* __restrict__ Bh, const uint16_t* __restrict__ Bl, long ldb,
    int nk,
    float* __restrict__ C, uint16_t* __restrict__ Ch, uint16_t* __restrict__ Cl,
    uint16_t* __restrict__ Cf, long ldc,
    int m0, int n0)
{
    extern __shared__ uint16_t sm[];
    const uint32_t uS = smem_u32(sm);

    const int tid = threadIdx.x;
    const int wid = tid >> 5, lane = tid & 31;
    const int wm = wid >> 1, wn = wid & 1;
    const int kkx = wid & 1;
    const int r = tid >> 1, h16 = (tid & 1) << 4;

    const uint32_t rowoff = ((uint32_t)r * LDS + h16) * 2;

    auto issue = [&](int kc, int st) {
        const uint16_t* a_h;
        if (CONCAT && kc >= 16)
            a_h = A1h + (size_t)(m0 + r) * 512 + (size_t)(kc - 16) * 32 + h16;
        else
            a_h = Ah + (size_t)(m0 + r) * lda + (size_t)kc * 32 + h16;
        const uint16_t* b_h = Bh + (size_t)(n0 + r) * ldb + (size_t)kc * 32 + h16;
        const uint16_t* b_l = Bl + (size_t)(n0 + r) * ldb + (size_t)kc * 32 + h16;
        const uint32_t base = uS + (uint32_t)st * STG_BYTES + rowoff;
        CP16(base + 0 * 128 * LDS * 2,      a_h);
        CP16(base + 0 * 128 * LDS * 2 + 16, a_h + 8);
        if (!F16) {
            const uint16_t* a_l = Al + (size_t)(m0 + r) * lda + (size_t)kc * 32 + h16;
            CP16(base + 1 * 128 * LDS * 2,      a_l);
            CP16(base + 1 * 128 * LDS * 2 + 16, a_l + 8);
        }
        CP16(base + 2 * 128 * LDS * 2,      b_h);
        CP16(base + 2 * 128 * LDS * 2 + 16, b_h + 8);
        CP16(base + 3 * 128 * LDS * 2,      b_l);
        CP16(base + 3 * 128 * LDS * 2 + 16, b_l + 8);
    };

    float acc[2][8][4] = {};

    issue(0, 0);
    CP_COMMIT();

    for (int kc = 0; kc < nk; ++kc) {
        const int st = kc & 1;
        CP_WAIT0();
        __syncthreads();
        if (kc + 1 < nk) { issue(kc + 1, st ^ 1); CP_COMMIT(); }

        const uint32_t sA  = uS + (uint32_t)st * STG_BYTES;
        const uint32_t sAl_ = sA + 128 * LDS * 2;
        const uint32_t sB  = sA + 2 * 128 * LDS * 2;
        const uint32_t sBl_ = sA + 3 * 128 * LDS * 2;

#pragma unroll
        for (int kk2 = 0; kk2 < 2; ++kk2) {
            const int kk = kk2 ^ kkx;   // address-level stagger only
            const uint32_t aoff =
                ((uint32_t)(wm * 32 + (lane & 15)) * LDS + kk * 16 + ((lane & 16) ? 8 : 0)) * 2;
            uint32_t ah[2][4], al[2][4];
            ldsm4(ah[0], sA + aoff);
            ldsm4(ah[1], sA + aoff + 16 * LDS * 2);
            if (!F16) {
                ldsm4(al[0], sAl_ + aoff);
                ldsm4(al[1], sAl_ + aoff + 16 * LDS * 2);
            }

            const uint32_t boff =
                ((uint32_t)(wn * 64 + (lane & 7) + ((lane & 16) ? 8 : 0)) * LDS
                 + kk * 16 + ((lane & 8) ? 8 : 0)) * 2;

#pragma unroll
            for (int jh = 0; jh < 2; ++jh) {
                uint32_t bh[4][2], bl[4][2];
#pragma unroll
                for (int jj = 0; jj < 2; ++jj) {
                    uint32_t tb[4], tl[4];
                    const uint32_t bo = boff + (jh * 2 + jj) * 16 * LDS * 2;
                    ldsm4(tb, sB + bo);
                    ldsm4(tl, sBl_ + bo);
                    bh[2 * jj][0] = tb[0]; bh[2 * jj][1] = tb[1];
                    bh[2 * jj + 1][0] = tb[2]; bh[2 * jj + 1][1] = tb[3];
                    bl[2 * jj][0] = tl[0]; bl[2 * jj][1] = tl[1];
                    bl[2 * jj + 1][0] = tl[2]; bl[2 * jj + 1][1] = tl[3];
                }
                if (F16) {
#pragma unroll
                    for (int im = 0; im < 2; ++im)
#pragma unroll
                        for (int j = 0; j < 4; ++j)
                            mma_f16(acc[im][jh * 4 + j], ah[im], bh[j]);
#pragma unroll
                    for (int im = 0; im < 2; ++im)
#pragma unroll
                        for (int j = 0; j < 4; ++j)
                            mma_f16(acc[im][jh * 4 + j], ah[im], bl[j]);
                } else {
#pragma unroll
                    for (int im = 0; im < 2; ++im)
#pragma unroll
                        for (int j = 0; j < 4; ++j)
                            mma_bf16(acc[im][jh * 4 + j], ah[im], bh[j]);
#pragma unroll
                    for (int im = 0; im < 2; ++im)
#pragma unroll
                        for (int j = 0; j < 4; ++j)
                            mma_bf16(acc[im][jh * 4 + j], ah[im], bl[j]);
#pragma unroll
                    for (int im = 0; im < 2; ++im)
#pragma unroll
                        for (int j = 0; j < 4; ++j)
                            mma_bf16(acc[im][jh * 4 + j], al[im], bh[j]);
                }
            }
        }
    }

    // epilogue
    const int g = lane >> 2, tg = lane & 3;
#pragma unroll
    for (int im = 0; im < 2; ++im) {
        const size_t row = (size_t)(m0 + wm * 32 + im * 16 + g);
#pragma unroll
        for (int j = 0; j < 8; ++j) {
            const size_t col = (size_t)(n0 + wn * 64 + j * 8 + tg * 2);
#pragma unroll
            for (int p = 0; p < 2; ++p) {
                const size_t rr = (row + p * 8) * ldc + col;
                const float v0 = acc[im][j][2 * p], v1 = acc[im][j][2 * p + 1];
                if (EPI == 0) {
                    *(float2*)(C + rr) = make_float2(v0, v1);
                } else if (EPI == 1) {
                    bf h0, l0, h1, l1;
                    split1(v0, h0, l0);
                    split1(v1, h1, l1);
                    *(uint32_t*)(Ch + rr) = pack2(h0, h1);
                    *(uint32_t*)(Cl + rr) = pack2(l0, l1);
                    *(uint32_t*)(Cf + rr) = pack2h(__float2half_rn(v0), __float2half_rn(v1));
                } else {
                    *(uint32_t*)(Cf + rr) = pack2h(__float2half_rn(v0), __float2half_rn(v1));
                }
            }
        }
    }
}

// ---------------------------------------------------------------------------
// GEMM kernels
// ---------------------------------------------------------------------------
__global__ void __launch_bounds__(256, 2) k_qproj() {
    gemm_core<0, 1, 0>((const uint16_t*)g_qinh, (const uint16_t*)g_qinl, nullptr, DIM,
                       (const uint16_t*)g_Winh, (const uint16_t*)g_Winl, DIM, 16,
                       nullptr, (uint16_t*)g_qh, (uint16_t*)g_ql, (uint16_t*)g_qfh,
                       DIM, blockIdx.y * 128, blockIdx.x * 128);
}
__global__ void __launch_bounds__(256, 2) k_scores() {
    if (blockIdx.x > blockIdx.y) return;   // fully masked causal tile
    const size_t qo = (size_t)blockIdx.z * SEQ * DIM;
    gemm_core<0, 0, 0>((const uint16_t*)(g_qh + qo), (const uint16_t*)(g_ql + qo), nullptr, DIM,
                       (const uint16_t*)(g_qh + qo), (const uint16_t*)(g_ql + qo), DIM, 16,
                       g_S + (size_t)blockIdx.z * SEQ * SEQ, nullptr, nullptr, nullptr,
                       SEQ, blockIdx.y * 128, blockIdx.x * 128);
}
__global__ void __launch_bounds__(256, 2) k_mix() {
    // Longest-K tiles first for the work-steal tail.
    const int b = blockIdx.z;
    const int ry = (SEQ / 128 - 1) - blockIdx.y;
    const int m0 = ry * 128, n0 = blockIdx.x * 128;
    const size_t wo = (size_t)b * SEQ * SEQ, qo = (size_t)b * DIM * SEQ;
    const size_t mo = (size_t)b * SEQ * DIM;
    gemm_core<0, 2, 1>((const uint16_t*)(g_Wfh + wo), nullptr, nullptr, SEQ,
                       (const uint16_t*)(g_qT16h + qo), (const uint16_t*)(g_qT16l + qo), SEQ,
                       m0 / 32 + 4,
                       nullptr, nullptr, nullptr, (uint16_t*)(g_mixfh + mo),
                       DIM, m0, n0);
}
__global__ void __launch_bounds__(256, 2) k_out(float* __restrict__ out) {
    gemm_core<1, 0, 1>((const uint16_t*)g_mixfh, nullptr, (const uint16_t*)g_qfh, DIM,
                       (const uint16_t*)g_Wo16h, (const uint16_t*)g_Wo16l, 2 * DIM, 32,
                       out, nullptr, nullptr, nullptr,
                       DIM, blockIdx.y * 128, blockIdx.x * 128);
}

// ---------------------------------------------------------------------------
// fp32 -> bf16 hi/lo split (query, W_in)
// ---------------------------------------------------------------------------
__global__ void __launch_bounds__(256) k_cvt(const float* __restrict__ src,
                                             bf* __restrict__ dh, bf* __restrict__ dl,
                                             size_t n) {
    size_t i = ((size_t)blockIdx.x * 256 + threadIdx.x) * 4;
    if (i >= n) return;
    float4 v = *(const float4*)(src + i);
    bf h0, l0, h1, l1, h2, l2, h3, l3;
    split1(v.x, h0, l0); split1(v.y, h1, l1);
    split1(v.z, h2, l2); split1(v.w, h3, l3);
    *(uint2*)(dh + i) = make_uint2(pack2(h0, h1), pack2(h2, h3));
    *(uint2*)(dl + i) = make_uint2(pack2(l0, l1), pack2(l2, l3));
}

// fp32 -> fp16 hi/lo split (W_out)
__global__ void __launch_bounds__(256) k_cvt16(const float* __restrict__ src,
                                               __half* __restrict__ dh, __half* __restrict__ dl,
                                               size_t n) {
    size_t i = ((size_t)blockIdx.x * 256 + threadIdx.x) * 4;
    if (i >= n) return;
    float4 v = *(const float4*)(src + i);
    float f[4] = {v.x, v.y, v.z, v.w};
    __half h[4], l[4];
#pragma unroll
    for (int k = 0; k < 4; ++k) {
        h[k] = __float2half_rn(f[k]);
        l[k] = __float2half_rn(f[k] - __half2float(h[k]));
    }
    *(uint2*)(dh + i) = make_uint2(pack2h(h[0], h[1]), pack2h(h[2], h[3]));
    *(uint2*)(dl + i) = make_uint2(pack2h(l[0], l[1]), pack2h(l[2], l[3]));
}

// ---------------------------------------------------------------------------
// Transpose: qT16[b][d][n] = q[b][n][d], bf16-pair -> fp16 hi/lo
// ---------------------------------------------------------------------------
__global__ void __launch_bounds__(256) k_transpose() {
    __shared__ float t[32][33];
    const int b = blockIdx.z, n0 = blockIdx.x * 32, d0 = blockIdx.y * 32;
    const int tx = threadIdx.x & 31, ty = threadIdx.x >> 5;
    const size_t so = (size_t)b * SEQ * DIM, to = (size_t)b * DIM * SEQ;
#pragma unroll
    for (int j = 0; j < 4; ++j) {
        const size_t idx = so + (size_t)(n0 + ty + 8 * j) * DIM + d0 + tx;
        t[ty + 8 * j][tx] = __bfloat162float(g_qh[idx]) + __bfloat162float(g_ql[idx]);
    }
    __syncthreads();
#pragma unroll
    for (int j = 0; j < 4; ++j) {
        const size_t idx = to + (size_t)(d0 + ty + 8 * j) * SEQ + n0 + tx;
        const float v = t[tx][ty + 8 * j];
        const __half fh = __float2half_rn(v);
        g_qT16h[idx] = fh;
        g_qT16l[idx] = __float2half_rn(v - __half2float(fh));
    }
}

// ---------------------------------------------------------------------------
// Softmax: row n over keys m < n (strict causal); emits fp16 weights (hi only).
// Thread t owns 8 contiguous elements; writes up to the 128-aligned mix limit.
// ---------------------------------------------------------------------------
__global__ void __launch_bounds__(256) k_softmax() {
    const int n = blockIdx.x, b = blockIdx.y;
    const size_t ro = ((size_t)b * SEQ + n) * SEQ;
    const float* row = g_S + ro;
    __half* wh = g_Wfh + ro;
    const int tid = threadIdx.x;
    const int mb = tid * 8;
    const int lim = (n / 128) * 128 + 128;
    __shared__ float red[8];

    float f[8];
    if (n > 0 && mb < n) {
        float4 v0 = *(const float4*)(row + mb);
        float4 v1 = *(const float4*)(row + mb + 4);
        f[0] = v0.x; f[1] = v0.y; f[2] = v0.z; f[3] = v0.w;
        f[4] = v1.x; f[5] = v1.y; f[6] = v1.z; f[7] = v1.w;
#pragma unroll
        for (int i = 0; i < 8; ++i)
            if (mb + i >= n) f[i] = -3.0e38f;
    } else {
#pragma unroll
        for (int i = 0; i < 8; ++i) f[i] = -3.0e38f;
    }

    if (n > 0) {
        float mx = -3.0e38f;
#pragma unroll
        for (int i = 0; i < 8; ++i) mx = fmaxf(mx, f[i]);
#pragma unroll
        for (int o = 16; o > 0; o >>= 1) mx = fmaxf(mx, __shfl_xor_sync(0xffffffffu, mx, o));
        if ((tid & 31) == 0) red[tid >> 5] = mx;
        __syncthreads();
        float bmx = red[0];
#pragma unroll
        for (int w = 1; w < 8; ++w) bmx = fmaxf(bmx, red[w]);
        __syncthreads();
        float s = 0.f;
#pragma unroll
        for (int i = 0; i < 8; ++i) {
            f[i] = (mb + i < n) ? __expf(f[i] - bmx) : 0.f;
            s += f[i];
        }
#pragma unroll
        for (int o = 16; o > 0; o >>= 1) s += __shfl_xor_sync(0xffffffffu, s, o);
        if ((tid & 31) == 0) red[tid >> 5] = s;
        __syncthreads();
        float tot = 0.f;
#pragma unroll
        for (int w = 0; w < 8; ++w) tot += red[w];
        const float inv = 1.f / tot;
#pragma unroll
        for (int i = 0; i < 8; ++i) f[i] *= inv;
    } else {
#pragma unroll
        for (int i = 0; i < 8; ++i) f[i] = 0.f;
    }

    if (mb < lim) {
        __half h[8];
#pragma unroll
        for (int i = 0; i < 8; ++i) h[i] = __float2half_rn(f[i]);
        *(uint4*)(wh + mb) = make_uint4(pack2h(h[0], h[1]), pack2h(h[2], h[3]),
                                        pack2h(h[4], h[5]), pack2h(h[6], h[7]));
    }
}

// ---------------------------------------------------------------------------
extern "C" void kernel_launch(void* const* d_in, const int* in_sizes, int n_in,
                              void* d_out, int out_size) {
    const float* query = (const float*)d_in[0];   // [16, 2048, 512]
    const float* W_in  = (const float*)d_in[1];   // [512, 512]
    const float* W_out = (const float*)d_in[2];   // [512, 1024]
    float* out = (float*)d_out;                   // [16, 2048, 512]

    const int smem = 2 * STG_BYTES;  // 81920
    static int init = 0;
    if (!init) {
        cudaFuncSetAttribute(k_qproj,  cudaFuncAttributeMaxDynamicSharedMemorySize, smem);
        cudaFuncSetAttribute(k_scores, cudaFuncAttributeMaxDynamicSharedMemorySize, smem);
        cudaFuncSetAttribute(k_mix,    cudaFuncAttributeMaxDynamicSharedMemorySize, smem);
        cudaFuncSetAttribute(k_out,    cudaFuncAttributeMaxDynamicSharedMemorySize, smem);
        init = 1;
    }

    bf *qinh, *qinl, *winh, *winl;
    __half *wo16h, *wo16l;
    cudaGetSymbolAddress((void**)&qinh,  g_qinh);
    cudaGetSymbolAddress((void**)&qinl,  g_qinl);
    cudaGetSymbolAddress((void**)&winh,  g_Winh);
    cudaGetSymbolAddress((void**)&winl,  g_Winl);
    cudaGetSymbolAddress((void**)&wo16h, g_Wo16h);
    cudaGetSymbolAddress((void**)&wo16l, g_Wo16l);

    const size_t nq = (size_t)BATCH * SEQ * DIM;
    k_cvt  <<<(unsigned)((nq / 4 + 255) / 256), 256>>>(query, qinh, qinl, nq);
    k_cvt  <<<(DIM * DIM / 4 + 255) / 256, 256>>>(W_in, winh, winl, DIM * DIM);
    k_cvt16<<<(DIM * 2 * DIM / 4 + 255) / 256, 256>>>(W_out, wo16h, wo16l, DIM * 2 * DIM);

    k_qproj    <<<dim3(DIM / 128, (BATCH * SEQ) / 128), 256, smem>>>();
    k_transpose<<<dim3(SEQ / 32, DIM / 32, BATCH),      256>>>();
    k_scores   <<<dim3(SEQ / 128, SEQ / 128, BATCH),    256, smem>>>();
    k_softmax  <<<dim3(SEQ, BATCH),                     256>>>();
    k_mix      <<<dim3(DIM / 128, SEQ / 128, BATCH),    256, smem>>>();
    k_out      <<<dim3(DIM / 128, (BATCH * SEQ) / 128), 256, smem>>>(out);
}

// round 15
// speedup vs baseline: 3.2799x; 1.2222x over previous
#include <cuda_runtime.h>
#include <cuda_bf16.h>
#include <cuda_fp16.h>
#include <cstdint>

#define BATCH 16
#define SEQ   2048
#define DIM   512
typedef __nv_bfloat16 bf;

// ---------------------------------------------------------------------------
// Persistent scratch (device globals — allocation-free per harness rules)
// ---------------------------------------------------------------------------
__device__ bf     g_qinh[(size_t)BATCH * SEQ * DIM];   // query bf16 hi/lo
__device__ bf     g_qinl[(size_t)BATCH * SEQ * DIM];
__device__ bf     g_Winh[DIM * DIM];
__device__ bf     g_Winl[DIM * DIM];
__device__ __half g_Wo16h[DIM * 2 * DIM];              // W_out fp16 hi
__device__ bf     g_qh  [(size_t)BATCH * SEQ * DIM];   // q bf16 hi/lo (scores)
__device__ bf     g_ql  [(size_t)BATCH * SEQ * DIM];
__device__ __half g_qfh [(size_t)BATCH * SEQ * DIM];   // q fp16 hi (k_out A)
__device__ __half g_qT16h[(size_t)BATCH * DIM * SEQ];  // q^T fp16 hi (mix B)
__device__ __half g_Wfh [(size_t)BATCH * SEQ * SEQ];   // softmax weights fp16 hi
__device__ __half g_mixfh[(size_t)BATCH * SEQ * DIM];  // mix fp16 hi
__device__ float  g_S   [(size_t)BATCH * SEQ * SEQ];   // fp32 scores

// ---------------------------------------------------------------------------
// PTX helpers (portable: ldmatrix / mma.sync / cp.async)
// ---------------------------------------------------------------------------
__device__ __forceinline__ uint32_t smem_u32(const void* p) {
    uint32_t a;
    asm("{ .reg .u64 t; cvta.to.shared.u64 t, %1; cvt.u32.u64 %0, t; }" : "=r"(a) : "l"(p));
    return a;
}
__device__ __forceinline__ void ldsm4(uint32_t* r, uint32_t addr) {
    asm volatile("ldmatrix.sync.aligned.m8n8.x4.shared.b16 {%0,%1,%2,%3}, [%4];"
                 : "=r"(r[0]), "=r"(r[1]), "=r"(r[2]), "=r"(r[3]) : "r"(addr));
}
__device__ __forceinline__ void mma_bf16(float* c, const uint32_t* a, const uint32_t* b) {
    asm volatile(
        "mma.sync.aligned.m16n8k16.row.col.f32.bf16.bf16.f32 "
        "{%0,%1,%2,%3}, {%4,%5,%6,%7}, {%8,%9}, {%0,%1,%2,%3};"
        : "+f"(c[0]), "+f"(c[1]), "+f"(c[2]), "+f"(c[3])
        : "r"(a[0]), "r"(a[1]), "r"(a[2]), "r"(a[3]), "r"(b[0]), "r"(b[1]));
}
__device__ __forceinline__ void mma_f16(float* c, const uint32_t* a, const uint32_t* b) {
    asm volatile(
        "mma.sync.aligned.m16n8k16.row.col.f32.f16.f16.f32 "
        "{%0,%1,%2,%3}, {%4,%5,%6,%7}, {%8,%9}, {%0,%1,%2,%3};"
        : "+f"(c[0]), "+f"(c[1]), "+f"(c[2]), "+f"(c[3])
        : "r"(a[0]), "r"(a[1]), "r"(a[2]), "r"(a[3]), "r"(b[0]), "r"(b[1]));
}
#define CP16(s, g)  asm volatile("cp.async.cg.shared.global [%0], [%1], 16;" :: "r"(s), "l"(g) : "memory")
#define CP_COMMIT() asm volatile("cp.async.commit_group;" ::: "memory")
#define CP_WAIT0()  asm volatile("cp.async.wait_group 0;" ::: "memory")

__device__ __forceinline__ void split1(float v, bf& h, bf& l) {
    h = __float2bfloat16_rn(v);
    l = __float2bfloat16_rn(v - __bfloat162float(h));
}
__device__ __forceinline__ uint32_t pack2(bf a, bf b) {
    return ((uint32_t)__bfloat16_as_ushort(b) << 16) | __bfloat16_as_ushort(a);
}
__device__ __forceinline__ uint32_t pack2h(__half a, __half b) {
    return ((uint32_t)__half_as_ushort(b) << 16) | __half_as_ushort(a);
}

// ---------------------------------------------------------------------------
// GEMM: C[128x128] = A @ B^T, fp32 accum, m16n8k16 mma.
// F16=0: bf16 3-pass split (ah*bh + ah*bl + al*bh) — qproj, scores.
// F16=1: fp16 1-pass (ah*bh only) — mix, out (post-softmax; error budget ok).
// Operands K-major 16-bit. K = nk*32. CONCAT: chunks>=16 read A1 (lda 512).
// EPI: 0 -> fp32 C; 1 -> bf16 (Ch,Cl) + fp16 Cf; 2 -> fp16 Cf only.
// 256 threads = 8 warps (4m x 2n), warp tile 32x64, 2-stage cp.async,
// one __syncthreads per chunk, 2 CTA/SM. Acc indices compile-time constant.
// ---------------------------------------------------------------------------
#define LDS 40  // 16-bit elems per smem row (80B; conflict-free ldmatrix)
#define STG_BYTES (4 * 128 * LDS * 2)  // one stage: Ah,Al,Bh,Bl regions

template<int CONCAT, int EPI, int F16>
__device__ __forceinline__ void gemm_core(
    const uint16_t* __restrict__ Ah, const uint16_t* __restrict__ Al,
    const uint16_t* __restrict__ A1h, long lda,
    const uint16_t* __restrict__ Bh, const uint16_t* __restrict__ Bl, long ldb,
    int nk,
    float* __restrict__ C, uint16_t* __restrict__ Ch, uint16_t* __restrict__ Cl,
    uint16_t* __restrict__ Cf, long ldc,
    int m0, int n0)
{
    extern __shared__ uint16_t sm[];
    const uint32_t uS = smem_u32(sm);

    const int tid = threadIdx.x;
    const int wid = tid >> 5, lane = tid & 31;
    const int wm = wid >> 1, wn = wid & 1;
    const int kkx = wid & 1;
    const int r = tid >> 1, h16 = (tid & 1) << 4;

    const uint32_t rowoff = ((uint32_t)r * LDS + h16) * 2;

    auto issue = [&](int kc, int st) {
        const uint16_t* a_h;
        if (CONCAT && kc >= 16)
            a_h = A1h + (size_t)(m0 + r) * 512 + (size_t)(kc - 16) * 32 + h16;
        else
            a_h = Ah + (size_t)(m0 + r) * lda + (size_t)kc * 32 + h16;
        const uint16_t* b_h = Bh + (size_t)(n0 + r) * ldb + (size_t)kc * 32 + h16;
        const uint32_t base = uS + (uint32_t)st * STG_BYTES + rowoff;
        CP16(base + 0 * 128 * LDS * 2,      a_h);
        CP16(base + 0 * 128 * LDS * 2 + 16, a_h + 8);
        CP16(base + 2 * 128 * LDS * 2,      b_h);
        CP16(base + 2 * 128 * LDS * 2 + 16, b_h + 8);
        if (!F16) {
            const uint16_t* a_l = Al + (size_t)(m0 + r) * lda + (size_t)kc * 32 + h16;
            const uint16_t* b_l = Bl + (size_t)(n0 + r) * ldb + (size_t)kc * 32 + h16;
            CP16(base + 1 * 128 * LDS * 2,      a_l);
            CP16(base + 1 * 128 * LDS * 2 + 16, a_l + 8);
            CP16(base + 3 * 128 * LDS * 2,      b_l);
            CP16(base + 3 * 128 * LDS * 2 + 16, b_l + 8);
        }
    };

    float acc[2][8][4] = {};

    issue(0, 0);
    CP_COMMIT();

    for (int kc = 0; kc < nk; ++kc) {
        const int st = kc & 1;
        CP_WAIT0();
        __syncthreads();
        if (kc + 1 < nk) { issue(kc + 1, st ^ 1); CP_COMMIT(); }

        const uint32_t sA  = uS + (uint32_t)st * STG_BYTES;
        const uint32_t sAl_ = sA + 128 * LDS * 2;
        const uint32_t sB  = sA + 2 * 128 * LDS * 2;
        const uint32_t sBl_ = sA + 3 * 128 * LDS * 2;

#pragma unroll
        for (int kk2 = 0; kk2 < 2; ++kk2) {
            const int kk = kk2 ^ kkx;   // address-level stagger only
            const uint32_t aoff =
                ((uint32_t)(wm * 32 + (lane & 15)) * LDS + kk * 16 + ((lane & 16) ? 8 : 0)) * 2;
            uint32_t ah[2][4], al[2][4];
            ldsm4(ah[0], sA + aoff);
            ldsm4(ah[1], sA + aoff + 16 * LDS * 2);
            if (!F16) {
                ldsm4(al[0], sAl_ + aoff);
                ldsm4(al[1], sAl_ + aoff + 16 * LDS * 2);
            }

            const uint32_t boff =
                ((uint32_t)(wn * 64 + (lane & 7) + ((lane & 16) ? 8 : 0)) * LDS
                 + kk * 16 + ((lane & 8) ? 8 : 0)) * 2;

#pragma unroll
            for (int jh = 0; jh < 2; ++jh) {
                uint32_t bh[4][2], bl[4][2];
#pragma unroll
                for (int jj = 0; jj < 2; ++jj) {
                    uint32_t tb[4];
                    const uint32_t bo = boff + (jh * 2 + jj) * 16 * LDS * 2;
                    ldsm4(tb, sB + bo);
                    bh[2 * jj][0] = tb[0]; bh[2 * jj][1] = tb[1];
                    bh[2 * jj + 1][0] = tb[2]; bh[2 * jj + 1][1] = tb[3];
                    if (!F16) {
                        uint32_t tl[4];
                        ldsm4(tl, sBl_ + bo);
                        bl[2 * jj][0] = tl[0]; bl[2 * jj][1] = tl[1];
                        bl[2 * jj + 1][0] = tl[2]; bl[2 * jj + 1][1] = tl[3];
                    }
                }
                if (F16) {
#pragma unroll
                    for (int im = 0; im < 2; ++im)
#pragma unroll
                        for (int j = 0; j < 4; ++j)
                            mma_f16(acc[im][jh * 4 + j], ah[im], bh[j]);
                } else {
#pragma unroll
                    for (int im = 0; im < 2; ++im)
#pragma unroll
                        for (int j = 0; j < 4; ++j)
                            mma_bf16(acc[im][jh * 4 + j], ah[im], bh[j]);
#pragma unroll
                    for (int im = 0; im < 2; ++im)
#pragma unroll
                        for (int j = 0; j < 4; ++j)
                            mma_bf16(acc[im][jh * 4 + j], ah[im], bl[j]);
#pragma unroll
                    for (int im = 0; im < 2; ++im)
#pragma unroll
                        for (int j = 0; j < 4; ++j)
                            mma_bf16(acc[im][jh * 4 + j], al[im], bh[j]);
                }
            }
        }
    }

    // epilogue
    const int g = lane >> 2, tg = lane & 3;
#pragma unroll
    for (int im = 0; im < 2; ++im) {
        const size_t row = (size_t)(m0 + wm * 32 + im * 16 + g);
#pragma unroll
        for (int j = 0; j < 8; ++j) {
            const size_t col = (size_t)(n0 + wn * 64 + j * 8 + tg * 2);
#pragma unroll
            for (int p = 0; p < 2; ++p) {
                const size_t rr = (row + p * 8) * ldc + col;
                const float v0 = acc[im][j][2 * p], v1 = acc[im][j][2 * p + 1];
                if (EPI == 0) {
                    *(float2*)(C + rr) = make_float2(v0, v1);
                } else if (EPI == 1) {
                    bf h0, l0, h1, l1;
                    split1(v0, h0, l0);
                    split1(v1, h1, l1);
                    *(uint32_t*)(Ch + rr) = pack2(h0, h1);
                    *(uint32_t*)(Cl + rr) = pack2(l0, l1);
                    *(uint32_t*)(Cf + rr) = pack2h(__float2half_rn(v0), __float2half_rn(v1));
                } else {
                    *(uint32_t*)(Cf + rr) = pack2h(__float2half_rn(v0), __float2half_rn(v1));
                }
            }
        }
    }
}

// ---------------------------------------------------------------------------
// GEMM kernels
// ---------------------------------------------------------------------------
__global__ void __launch_bounds__(256, 2) k_qproj() {
    gemm_core<0, 1, 0>((const uint16_t*)g_qinh, (const uint16_t*)g_qinl, nullptr, DIM,
                       (const uint16_t*)g_Winh, (const uint16_t*)g_Winl, DIM, 16,
                       nullptr, (uint16_t*)g_qh, (uint16_t*)g_ql, (uint16_t*)g_qfh,
                       DIM, blockIdx.y * 128, blockIdx.x * 128);
}
__global__ void __launch_bounds__(256, 2) k_scores() {
    if (blockIdx.x > blockIdx.y) return;   // fully masked causal tile
    const size_t qo = (size_t)blockIdx.z * SEQ * DIM;
    gemm_core<0, 0, 0>((const uint16_t*)(g_qh + qo), (const uint16_t*)(g_ql + qo), nullptr, DIM,
                       (const uint16_t*)(g_qh + qo), (const uint16_t*)(g_ql + qo), DIM, 16,
                       g_S + (size_t)blockIdx.z * SEQ * SEQ, nullptr, nullptr, nullptr,
                       SEQ, blockIdx.y * 128, blockIdx.x * 128);
}
__global__ void __launch_bounds__(256, 2) k_mix() {
    // Longest-K tiles first for the work-steal tail.
    const int b = blockIdx.z;
    const int ry = (SEQ / 128 - 1) - blockIdx.y;
    const int m0 = ry * 128, n0 = blockIdx.x * 128;
    const size_t wo = (size_t)b * SEQ * SEQ, qo = (size_t)b * DIM * SEQ;
    const size_t mo = (size_t)b * SEQ * DIM;
    gemm_core<0, 2, 1>((const uint16_t*)(g_Wfh + wo), nullptr, nullptr, SEQ,
                       (const uint16_t*)(g_qT16h + qo), nullptr, SEQ,
                       m0 / 32 + 4,
                       nullptr, nullptr, nullptr, (uint16_t*)(g_mixfh + mo),
                       DIM, m0, n0);
}
__global__ void __launch_bounds__(256, 2) k_out(float* __restrict__ out) {
    gemm_core<1, 0, 1>((const uint16_t*)g_mixfh, nullptr, (const uint16_t*)g_qfh, DIM,
                       (const uint16_t*)g_Wo16h, nullptr, 2 * DIM, 32,
                       out, nullptr, nullptr, nullptr,
                       DIM, blockIdx.y * 128, blockIdx.x * 128);
}

// ---------------------------------------------------------------------------
// fp32 -> bf16 hi/lo split (query, W_in)
// ---------------------------------------------------------------------------
__global__ void __launch_bounds__(256) k_cvt(const float* __restrict__ src,
                                             bf* __restrict__ dh, bf* __restrict__ dl,
                                             size_t n) {
    size_t i = ((size_t)blockIdx.x * 256 + threadIdx.x) * 4;
    if (i >= n) return;
    float4 v = *(const float4*)(src + i);
    bf h0, l0, h1, l1, h2, l2, h3, l3;
    split1(v.x, h0, l0); split1(v.y, h1, l1);
    split1(v.z, h2, l2); split1(v.w, h3, l3);
    *(uint2*)(dh + i) = make_uint2(pack2(h0, h1), pack2(h2, h3));
    *(uint2*)(dl + i) = make_uint2(pack2(l0, l1), pack2(l2, l3));
}

// fp32 -> fp16 hi (W_out)
__global__ void __launch_bounds__(256) k_cvt16(const float* __restrict__ src,
                                               __half* __restrict__ dh, size_t n) {
    size_t i = ((size_t)blockIdx.x * 256 + threadIdx.x) * 4;
    if (i >= n) return;
    float4 v = *(const float4*)(src + i);
    *(uint2*)(dh + i) = make_uint2(
        pack2h(__float2half_rn(v.x), __float2half_rn(v.y)),
        pack2h(__float2half_rn(v.z), __float2half_rn(v.w)));
}

// ---------------------------------------------------------------------------
// Transpose: qT16[b][d][n] = q[b][n][d], bf16-pair -> fp16 hi only
// ---------------------------------------------------------------------------
__global__ void __launch_bounds__(256) k_transpose() {
    __shared__ float t[32][33];
    const int b = blockIdx.z, n0 = blockIdx.x * 32, d0 = blockIdx.y * 32;
    const int tx = threadIdx.x & 31, ty = threadIdx.x >> 5;
    const size_t so = (size_t)b * SEQ * DIM, to = (size_t)b * DIM * SEQ;
#pragma unroll
    for (int j = 0; j < 4; ++j) {
        const size_t idx = so + (size_t)(n0 + ty + 8 * j) * DIM + d0 + tx;
        t[ty + 8 * j][tx] = __bfloat162float(g_qh[idx]) + __bfloat162float(g_ql[idx]);
    }
    __syncthreads();
#pragma unroll
    for (int j = 0; j < 4; ++j) {
        const size_t idx = to + (size_t)(d0 + ty + 8 * j) * SEQ + n0 + tx;
        g_qT16h[idx] = __float2half_rn(t[tx][ty + 8 * j]);
    }
}

// ---------------------------------------------------------------------------
// Softmax: row n over keys m < n (strict causal); emits fp16 weights (hi only).
// Thread t owns 8 contiguous elements; writes up to the 128-aligned mix limit.
// ---------------------------------------------------------------------------
__global__ void __launch_bounds__(256) k_softmax() {
    const int n = blockIdx.x, b = blockIdx.y;
    const size_t ro = ((size_t)b * SEQ + n) * SEQ;
    const float* row = g_S + ro;
    __half* wh = g_Wfh + ro;
    const int tid = threadIdx.x;
    const int mb = tid * 8;
    const int lim = (n / 128) * 128 + 128;
    __shared__ float red[8];

    float f[8];
    if (n > 0 && mb < n) {
        float4 v0 = *(const float4*)(row + mb);
        float4 v1 = *(const float4*)(row + mb + 4);
        f[0] = v0.x; f[1] = v0.y; f[2] = v0.z; f[3] = v0.w;
        f[4] = v1.x; f[5] = v1.y; f[6] = v1.z; f[7] = v1.w;
#pragma unroll
        for (int i = 0; i < 8; ++i)
            if (mb + i >= n) f[i] = -3.0e38f;
    } else {
#pragma unroll
        for (int i = 0; i < 8; ++i) f[i] = -3.0e38f;
    }

    if (n > 0) {
        float mx = -3.0e38f;
#pragma unroll
        for (int i = 0; i < 8; ++i) mx = fmaxf(mx, f[i]);
#pragma unroll
        for (int o = 16; o > 0; o >>= 1) mx = fmaxf(mx, __shfl_xor_sync(0xffffffffu, mx, o));
        if ((tid & 31) == 0) red[tid >> 5] = mx;
        __syncthreads();
        float bmx = red[0];
#pragma unroll
        for (int w = 1; w < 8; ++w) bmx = fmaxf(bmx, red[w]);
        __syncthreads();
        float s = 0.f;
#pragma unroll
        for (int i = 0; i < 8; ++i) {
            f[i] = (mb + i < n) ? __expf(f[i] - bmx) : 0.f;
            s += f[i];
        }
#pragma unroll
        for (int o = 16; o > 0; o >>= 1) s += __shfl_xor_sync(0xffffffffu, s, o);
        if ((tid & 31) == 0) red[tid >> 5] = s;
        __syncthreads();
        float tot = 0.f;
#pragma unroll
        for (int w = 0; w < 8; ++w) tot += red[w];
        const float inv = 1.f / tot;
#pragma unroll
        for (int i = 0; i < 8; ++i) f[i] *= inv;
    } else {
#pragma unroll
        for (int i = 0; i < 8; ++i) f[i] = 0.f;
    }

    if (mb < lim) {
        __half h[8];
#pragma unroll
        for (int i = 0; i < 8; ++i) h[i] = __float2half_rn(f[i]);
        *(uint4*)(wh + mb) = make_uint4(pack2h(h[0], h[1]), pack2h(h[2], h[3]),
                                        pack2h(h[4], h[5]), pack2h(h[6], h[7]));
    }
}

// ---------------------------------------------------------------------------
extern "C" void kernel_launch(void* const* d_in, const int* in_sizes, int n_in,
                              void* d_out, int out_size) {
    const float* query = (const float*)d_in[0];   // [16, 2048, 512]
    const float* W_in  = (const float*)d_in[1];   // [512, 512]
    const float* W_out = (const float*)d_in[2];   // [512, 1024]
    float* out = (float*)d_out;                   // [16, 2048, 512]

    const int smem = 2 * STG_BYTES;  // 81920
    static int init = 0;
    if (!init) {
        cudaFuncSetAttribute(k_qproj,  cudaFuncAttributeMaxDynamicSharedMemorySize, smem);
        cudaFuncSetAttribute(k_scores, cudaFuncAttributeMaxDynamicSharedMemorySize, smem);
        cudaFuncSetAttribute(k_mix,    cudaFuncAttributeMaxDynamicSharedMemorySize, smem);
        cudaFuncSetAttribute(k_out,    cudaFuncAttributeMaxDynamicSharedMemorySize, smem);
        init = 1;
    }

    bf *qinh, *qinl, *winh, *winl;
    __half *wo16h;
    cudaGetSymbolAddress((void**)&qinh,  g_qinh);
    cudaGetSymbolAddress((void**)&qinl,  g_qinl);
    cudaGetSymbolAddress((void**)&winh,  g_Winh);
    cudaGetSymbolAddress((void**)&winl,  g_Winl);
    cudaGetSymbolAddress((void**)&wo16h, g_Wo16h);

    const size_t nq = (size_t)BATCH * SEQ * DIM;
    k_cvt  <<<(unsigned)((nq / 4 + 255) / 256), 256>>>(query, qinh, qinl, nq);
    k_cvt  <<<(DIM * DIM / 4 + 255) / 256, 256>>>(W_in, winh, winl, DIM * DIM);
    k_cvt16<<<(DIM * 2 * DIM / 4 + 255) / 256, 256>>>(W_out, wo16h, DIM * 2 * DIM);

    k_qproj    <<<dim3(DIM / 128, (BATCH * SEQ) / 128), 256, smem>>>();
    k_transpose<<<dim3(SEQ / 32, DIM / 32, BATCH),      256>>>();
    k_scores   <<<dim3(SEQ / 128, SEQ / 128, BATCH),    256, smem>>>();
    k_softmax  <<<dim3(SEQ, BATCH),                     256>>>();
    k_mix      <<<dim3(DIM / 128, SEQ / 128, BATCH),    256, smem>>>();
    k_out      <<<dim3(DIM / 128, (BATCH * SEQ) / 128), 256, smem>>>(out);
}

// round 16
// speedup vs baseline: 3.3604x; 1.0245x over previous
#include <cuda_runtime.h>
#include <cuda_fp16.h>
#include <cstdint>

#define BATCH 16
#define SEQ   2048
#define DIM   512

// ---------------------------------------------------------------------------
// Persistent scratch (device globals — allocation-free per harness rules)
// ---------------------------------------------------------------------------
__device__ __half g_qinfh[(size_t)BATCH * SEQ * DIM];  // query fp16 hi/lo
__device__ __half g_qinfl[(size_t)BATCH * SEQ * DIM];
__device__ __half g_Winfh[DIM * DIM];                  // W_in fp16 hi/lo
__device__ __half g_Winfl[DIM * DIM];
__device__ __half g_Wo16h[DIM * 2 * DIM];              // W_out fp16 hi
__device__ __half g_qfh [(size_t)BATCH * SEQ * DIM];   // q fp16 hi/lo
__device__ __half g_qfl [(size_t)BATCH * SEQ * DIM];
__device__ __half g_qT16h[(size_t)BATCH * DIM * SEQ];  // q^T fp16 hi (mix B)
__device__ __half g_Wfh [(size_t)BATCH * SEQ * SEQ];   // softmax weights fp16 hi
__device__ __half g_mixfh[(size_t)BATCH * SEQ * DIM];  // mix fp16 hi
__device__ float  g_S   [(size_t)BATCH * SEQ * SEQ];   // fp32 scores

// ---------------------------------------------------------------------------
// PTX helpers (portable: ldmatrix / mma.sync / cp.async)
// ---------------------------------------------------------------------------
__device__ __forceinline__ uint32_t smem_u32(const void* p) {
    uint32_t a;
    asm("{ .reg .u64 t; cvta.to.shared.u64 t, %1; cvt.u32.u64 %0, t; }" : "=r"(a) : "l"(p));
    return a;
}
__device__ __forceinline__ void ldsm4(uint32_t* r, uint32_t addr) {
    asm volatile("ldmatrix.sync.aligned.m8n8.x4.shared.b16 {%0,%1,%2,%3}, [%4];"
                 : "=r"(r[0]), "=r"(r[1]), "=r"(r[2]), "=r"(r[3]) : "r"(addr));
}
__device__ __forceinline__ void mma_f16(float* c, const uint32_t* a, const uint32_t* b) {
    asm volatile(
        "mma.sync.aligned.m16n8k16.row.col.f32.f16.f16.f32 "
        "{%0,%1,%2,%3}, {%4,%5,%6,%7}, {%8,%9}, {%0,%1,%2,%3};"
        : "+f"(c[0]), "+f"(c[1]), "+f"(c[2]), "+f"(c[3])
        : "r"(a[0]), "r"(a[1]), "r"(a[2]), "r"(a[3]), "r"(b[0]), "r"(b[1]));
}
#define CP16(s, g)  asm volatile("cp.async.cg.shared.global [%0], [%1], 16;" :: "r"(s), "l"(g) : "memory")
#define CP_COMMIT() asm volatile("cp.async.commit_group;" ::: "memory")
#define CP_WAIT0()  asm volatile("cp.async.wait_group 0;" ::: "memory")

__device__ __forceinline__ void split1h(float v, __half& h, __half& l) {
    h = __float2half_rn(v);
    l = __float2half_rn(v - __half2float(h));
}
__device__ __forceinline__ uint32_t pack2h(__half a, __half b) {
    return ((uint32_t)__half_as_ushort(b) << 16) | __half_as_ushort(a);
}

// ---------------------------------------------------------------------------
// GEMM: C[128x128] = A @ B^T, fp32 accum, fp16 m16n8k16 mma.
// PASS3=1: 3-pass hi/lo split (ah*bh + ah*bl + al*bh) — qproj, scores.
// PASS3=0: 1-pass (ah*bh) — mix, out (post-softmax; error budget verified).
// Operands K-major fp16. K = nk*32. CONCAT: chunks>=16 read A1 (lda 512).
// EPI: 0 -> fp32 C; 1 -> fp16 hi/lo (Ch, Cl); 2 -> fp16 hi only (Ch).
// 256 threads = 8 warps (4m x 2n), warp tile 32x64, 2-stage cp.async,
// one __syncthreads per chunk, 2 CTA/SM. Acc indices compile-time constant.
// ---------------------------------------------------------------------------
#define LDS 40  // 16-bit elems per smem row (80B; conflict-free ldmatrix)
#define STG_BYTES (4 * 128 * LDS * 2)  // one stage: Ah,Al,Bh,Bl regions

template<int CONCAT, int EPI, int PASS3>
__device__ __forceinline__ void gemm_core(
    const __half* __restrict__ Ah, const __half* __restrict__ Al,
    const __half* __restrict__ A1h, long lda,
    const __half* __restrict__ Bh, const __half* __restrict__ Bl, long ldb,
    int nk,
    float* __restrict__ C, __half* __restrict__ Ch, __half* __restrict__ Cl,
    long ldc, int m0, int n0)
{
    extern __shared__ __half sm[];
    const uint32_t uS = smem_u32(sm);

    const int tid = threadIdx.x;
    const int wid = tid >> 5, lane = tid & 31;
    const int wm = wid >> 1, wn = wid & 1;
    const int kkx = wid & 1;
    const int r = tid >> 1, h16 = (tid & 1) << 4;

    const uint32_t rowoff = ((uint32_t)r * LDS + h16) * 2;

    auto issue = [&](int kc, int st) {
        const __half* a_h;
        if (CONCAT && kc >= 16)
            a_h = A1h + (size_t)(m0 + r) * 512 + (size_t)(kc - 16) * 32 + h16;
        else
            a_h = Ah + (size_t)(m0 + r) * lda + (size_t)kc * 32 + h16;
        const __half* b_h = Bh + (size_t)(n0 + r) * ldb + (size_t)kc * 32 + h16;
        const uint32_t base = uS + (uint32_t)st * STG_BYTES + rowoff;
        CP16(base + 0 * 128 * LDS * 2,      a_h);
        CP16(base + 0 * 128 * LDS * 2 + 16, a_h + 8);
        CP16(base + 2 * 128 * LDS * 2,      b_h);
        CP16(base + 2 * 128 * LDS * 2 + 16, b_h + 8);
        if (PASS3) {
            const __half* a_l = Al + (size_t)(m0 + r) * lda + (size_t)kc * 32 + h16;
            const __half* b_l = Bl + (size_t)(n0 + r) * ldb + (size_t)kc * 32 + h16;
            CP16(base + 1 * 128 * LDS * 2,      a_l);
            CP16(base + 1 * 128 * LDS * 2 + 16, a_l + 8);
            CP16(base + 3 * 128 * LDS * 2,      b_l);
            CP16(base + 3 * 128 * LDS * 2 + 16, b_l + 8);
        }
    };

    float acc[2][8][4] = {};

    issue(0, 0);
    CP_COMMIT();

    for (int kc = 0; kc < nk; ++kc) {
        const int st = kc & 1;
        CP_WAIT0();
        __syncthreads();
        if (kc + 1 < nk) { issue(kc + 1, st ^ 1); CP_COMMIT(); }

        const uint32_t sA  = uS + (uint32_t)st * STG_BYTES;
        const uint32_t sAl_ = sA + 128 * LDS * 2;
        const uint32_t sB  = sA + 2 * 128 * LDS * 2;
        const uint32_t sBl_ = sA + 3 * 128 * LDS * 2;

#pragma unroll
        for (int kk2 = 0; kk2 < 2; ++kk2) {
            const int kk = kk2 ^ kkx;   // address-level stagger only
            const uint32_t aoff =
                ((uint32_t)(wm * 32 + (lane & 15)) * LDS + kk * 16 + ((lane & 16) ? 8 : 0)) * 2;
            uint32_t ah[2][4], al[2][4];
            ldsm4(ah[0], sA + aoff);
            ldsm4(ah[1], sA + aoff + 16 * LDS * 2);
            if (PASS3) {
                ldsm4(al[0], sAl_ + aoff);
                ldsm4(al[1], sAl_ + aoff + 16 * LDS * 2);
            }

            const uint32_t boff =
                ((uint32_t)(wn * 64 + (lane & 7) + ((lane & 16) ? 8 : 0)) * LDS
                 + kk * 16 + ((lane & 8) ? 8 : 0)) * 2;

#pragma unroll
            for (int jh = 0; jh < 2; ++jh) {
                uint32_t bh[4][2], bl[4][2];
#pragma unroll
                for (int jj = 0; jj < 2; ++jj) {
                    uint32_t tb[4];
                    const uint32_t bo = boff + (jh * 2 + jj) * 16 * LDS * 2;
                    ldsm4(tb, sB + bo);
                    bh[2 * jj][0] = tb[0]; bh[2 * jj][1] = tb[1];
                    bh[2 * jj + 1][0] = tb[2]; bh[2 * jj + 1][1] = tb[3];
                    if (PASS3) {
                        uint32_t tl[4];
                        ldsm4(tl, sBl_ + bo);
                        bl[2 * jj][0] = tl[0]; bl[2 * jj][1] = tl[1];
                        bl[2 * jj + 1][0] = tl[2]; bl[2 * jj + 1][1] = tl[3];
                    }
                }
#pragma unroll
                for (int im = 0; im < 2; ++im)
#pragma unroll
                    for (int j = 0; j < 4; ++j)
                        mma_f16(acc[im][jh * 4 + j], ah[im], bh[j]);
                if (PASS3) {
#pragma unroll
                    for (int im = 0; im < 2; ++im)
#pragma unroll
                        for (int j = 0; j < 4; ++j)
                            mma_f16(acc[im][jh * 4 + j], ah[im], bl[j]);
#pragma unroll
                    for (int im = 0; im < 2; ++im)
#pragma unroll
                        for (int j = 0; j < 4; ++j)
                            mma_f16(acc[im][jh * 4 + j], al[im], bh[j]);
                }
            }
        }
    }

    // epilogue
    const int g = lane >> 2, tg = lane & 3;
#pragma unroll
    for (int im = 0; im < 2; ++im) {
        const size_t row = (size_t)(m0 + wm * 32 + im * 16 + g);
#pragma unroll
        for (int j = 0; j < 8; ++j) {
            const size_t col = (size_t)(n0 + wn * 64 + j * 8 + tg * 2);
#pragma unroll
            for (int p = 0; p < 2; ++p) {
                const size_t rr = (row + p * 8) * ldc + col;
                const float v0 = acc[im][j][2 * p], v1 = acc[im][j][2 * p + 1];
                if (EPI == 0) {
                    *(float2*)(C + rr) = make_float2(v0, v1);
                } else if (EPI == 1) {
                    __half h0, l0, h1, l1;
                    split1h(v0, h0, l0);
                    split1h(v1, h1, l1);
                    *(uint32_t*)(Ch + rr) = pack2h(h0, h1);
                    *(uint32_t*)(Cl + rr) = pack2h(l0, l1);
                } else {
                    *(uint32_t*)(Ch + rr) = pack2h(__float2half_rn(v0), __float2half_rn(v1));
                }
            }
        }
    }
}

// ---------------------------------------------------------------------------
// GEMM kernels
// ---------------------------------------------------------------------------
__global__ void __launch_bounds__(256, 2) k_qproj() {
    gemm_core<0, 1, 1>(g_qinfh, g_qinfl, nullptr, DIM,
                       g_Winfh, g_Winfl, DIM, 16,
                       nullptr, g_qfh, g_qfl,
                       DIM, blockIdx.y * 128, blockIdx.x * 128);
}
__global__ void __launch_bounds__(256, 2) k_scores() {
    if (blockIdx.x > blockIdx.y) return;   // fully masked causal tile
    const size_t qo = (size_t)blockIdx.z * SEQ * DIM;
    gemm_core<0, 0, 1>(g_qfh + qo, g_qfl + qo, nullptr, DIM,
                       g_qfh + qo, g_qfl + qo, DIM, 16,
                       g_S + (size_t)blockIdx.z * SEQ * SEQ, nullptr, nullptr,
                       SEQ, blockIdx.y * 128, blockIdx.x * 128);
}
__global__ void __launch_bounds__(256, 2) k_mix() {
    // Longest-K tiles first for the work-steal tail.
    const int b = blockIdx.z;
    const int ry = (SEQ / 128 - 1) - blockIdx.y;
    const int m0 = ry * 128, n0 = blockIdx.x * 128;
    const size_t wo = (size_t)b * SEQ * SEQ, qo = (size_t)b * DIM * SEQ;
    const size_t mo = (size_t)b * SEQ * DIM;
    gemm_core<0, 2, 0>(g_Wfh + wo, nullptr, nullptr, SEQ,
                       g_qT16h + qo, nullptr, SEQ,
                       m0 / 32 + 4,
                       nullptr, g_mixfh + mo, nullptr,
                       DIM, m0, n0);
}
__global__ void __launch_bounds__(256, 2) k_out(float* __restrict__ out) {
    gemm_core<1, 0, 0>(g_mixfh, nullptr, g_qfh, DIM,
                       g_Wo16h, nullptr, 2 * DIM, 32,
                       out, nullptr, nullptr,
                       DIM, blockIdx.y * 128, blockIdx.x * 128);
}

// ---------------------------------------------------------------------------
// fp32 -> fp16 hi/lo split (query, W_in)
// ---------------------------------------------------------------------------
__global__ void __launch_bounds__(256) k_cvt(const float* __restrict__ src,
                                             __half* __restrict__ dh,
                                             __half* __restrict__ dl, size_t n) {
    size_t i = ((size_t)blockIdx.x * 256 + threadIdx.x) * 4;
    if (i >= n) return;
    float4 v = *(const float4*)(src + i);
    __half h[4], l[4];
    split1h(v.x, h[0], l[0]); split1h(v.y, h[1], l[1]);
    split1h(v.z, h[2], l[2]); split1h(v.w, h[3], l[3]);
    *(uint2*)(dh + i) = make_uint2(pack2h(h[0], h[1]), pack2h(h[2], h[3]));
    *(uint2*)(dl + i) = make_uint2(pack2h(l[0], l[1]), pack2h(l[2], l[3]));
}

// fp32 -> fp16 hi (W_out)
__global__ void __launch_bounds__(256) k_cvt16(const float* __restrict__ src,
                                               __half* __restrict__ dh, size_t n) {
    size_t i = ((size_t)blockIdx.x * 256 + threadIdx.x) * 4;
    if (i >= n) return;
    float4 v = *(const float4*)(src + i);
    *(uint2*)(dh + i) = make_uint2(
        pack2h(__float2half_rn(v.x), __float2half_rn(v.y)),
        pack2h(__float2half_rn(v.z), __float2half_rn(v.w)));
}

// ---------------------------------------------------------------------------
// Transpose: qT16[b][d][n] = qfh[b][n][d]  (fp16 copy-transpose)
// ---------------------------------------------------------------------------
__global__ void __launch_bounds__(256) k_transpose() {
    __shared__ __half t[32][33];
    const int b = blockIdx.z, n0 = blockIdx.x * 32, d0 = blockIdx.y * 32;
    const int tx = threadIdx.x & 31, ty = threadIdx.x >> 5;
    const size_t so = (size_t)b * SEQ * DIM, to = (size_t)b * DIM * SEQ;
#pragma unroll
    for (int j = 0; j < 4; ++j)
        t[ty + 8 * j][tx] = g_qfh[so + (size_t)(n0 + ty + 8 * j) * DIM + d0 + tx];
    __syncthreads();
#pragma unroll
    for (int j = 0; j < 4; ++j)
        g_qT16h[to + (size_t)(d0 + ty + 8 * j) * SEQ + n0 + tx] = t[tx][ty + 8 * j];
}

// ---------------------------------------------------------------------------
// Softmax: row n over keys m < n (strict causal); emits fp16 weights (hi only).
// Thread t owns 8 contiguous elements; streaming loads (rows read once).
// Writes only up to the 128-aligned k_mix limit.
// ---------------------------------------------------------------------------
__global__ void __launch_bounds__(256) k_softmax() {
    const int n = blockIdx.x, b = blockIdx.y;
    const size_t ro = ((size_t)b * SEQ + n) * SEQ;
    const float* row = g_S + ro;
    __half* wh = g_Wfh + ro;
    const int tid = threadIdx.x;
    const int mb = tid * 8;
    const int lim = (n / 128) * 128 + 128;
    __shared__ float red[8];

    float f[8];
    if (n > 0 && mb < n) {
        float4 v0 = __ldcs((const float4*)(row + mb));
        float4 v1 = __ldcs((const float4*)(row + mb + 4));
        f[0] = v0.x; f[1] = v0.y; f[2] = v0.z; f[3] = v0.w;
        f[4] = v1.x; f[5] = v1.y; f[6] = v1.z; f[7] = v1.w;
#pragma unroll
        for (int i = 0; i < 8; ++i)
            if (mb + i >= n) f[i] = -3.0e38f;
    } else {
#pragma unroll
        for (int i = 0; i < 8; ++i) f[i] = -3.0e38f;
    }

    if (n > 0) {
        float mx = -3.0e38f;
#pragma unroll
        for (int i = 0; i < 8; ++i) mx = fmaxf(mx, f[i]);
#pragma unroll
        for (int o = 16; o > 0; o >>= 1) mx = fmaxf(mx, __shfl_xor_sync(0xffffffffu, mx, o));
        if ((tid & 31) == 0) red[tid >> 5] = mx;
        __syncthreads();
        float bmx = red[0];
#pragma unroll
        for (int w = 1; w < 8; ++w) bmx = fmaxf(bmx, red[w]);
        __syncthreads();
        float s = 0.f;
#pragma unroll
        for (int i = 0; i < 8; ++i) {
            f[i] = (mb + i < n) ? __expf(f[i] - bmx) : 0.f;
            s += f[i];
        }
#pragma unroll
        for (int o = 16; o > 0; o >>= 1) s += __shfl_xor_sync(0xffffffffu, s, o);
        if ((tid & 31) == 0) red[tid >> 5] = s;
        __syncthreads();
        float tot = 0.f;
#pragma unroll
        for (int w = 0; w < 8; ++w) tot += red[w];
        const float inv = 1.f / tot;
#pragma unroll
        for (int i = 0; i < 8; ++i) f[i] *= inv;
    } else {
#pragma unroll
        for (int i = 0; i < 8; ++i) f[i] = 0.f;
    }

    if (mb < lim) {
        __half h[8];
#pragma unroll
        for (int i = 0; i < 8; ++i) h[i] = __float2half_rn(f[i]);
        *(uint4*)(wh + mb) = make_uint4(pack2h(h[0], h[1]), pack2h(h[2], h[3]),
                                        pack2h(h[4], h[5]), pack2h(h[6], h[7]));
    }
}

// ---------------------------------------------------------------------------
extern "C" void kernel_launch(void* const* d_in, const int* in_sizes, int n_in,
                              void* d_out, int out_size) {
    const float* query = (const float*)d_in[0];   // [16, 2048, 512]
    const float* W_in  = (const float*)d_in[1];   // [512, 512]
    const float* W_out = (const float*)d_in[2];   // [512, 1024]
    float* out = (float*)d_out;                   // [16, 2048, 512]

    const int smem = 2 * STG_BYTES;  // 81920
    static int init = 0;
    if (!init) {
        cudaFuncSetAttribute(k_qproj,  cudaFuncAttributeMaxDynamicSharedMemorySize, smem);
        cudaFuncSetAttribute(k_scores, cudaFuncAttributeMaxDynamicSharedMemorySize, smem);
        cudaFuncSetAttribute(k_mix,    cudaFuncAttributeMaxDynamicSharedMemorySize, smem);
        cudaFuncSetAttribute(k_out,    cudaFuncAttributeMaxDynamicSharedMemorySize, smem);
        init = 1;
    }

    __half *qinfh, *qinfl, *winfh, *winfl, *wo16h;
    cudaGetSymbolAddress((void**)&qinfh, g_qinfh);
    cudaGetSymbolAddress((void**)&qinfl, g_qinfl);
    cudaGetSymbolAddress((void**)&winfh, g_Winfh);
    cudaGetSymbolAddress((void**)&winfl, g_Winfl);
    cudaGetSymbolAddress((void**)&wo16h, g_Wo16h);

    const size_t nq = (size_t)BATCH * SEQ * DIM;
    k_cvt  <<<(unsigned)((nq / 4 + 255) / 256), 256>>>(query, qinfh, qinfl, nq);
    k_cvt  <<<(DIM * DIM / 4 + 255) / 256, 256>>>(W_in, winfh, winfl, DIM * DIM);
    k_cvt16<<<(DIM * 2 * DIM / 4 + 255) / 256, 256>>>(W_out, wo16h, DIM * 2 * DIM);

    k_qproj    <<<dim3(DIM / 128, (BATCH * SEQ) / 128), 256, smem>>>();
    k_transpose<<<dim3(SEQ / 32, DIM / 32, BATCH),      256>>>();
    k_scores   <<<dim3(SEQ / 128, SEQ / 128, BATCH),    256, smem>>>();
    k_softmax  <<<dim3(SEQ, BATCH),                     256>>>();
    k_mix      <<<dim3(DIM / 128, SEQ / 128, BATCH),    256, smem>>>();
    k_out      <<<dim3(DIM / 128, (BATCH * SEQ) / 128), 256, smem>>>(out);
}

// round 17
// speedup vs baseline: 3.8042x; 1.1321x over previous
#include <cuda_runtime.h>
#include <cuda_fp16.h>
#include <cstdint>

#define BATCH 16
#define SEQ   2048
#define DIM   512

// ---------------------------------------------------------------------------
// Persistent scratch (device globals — allocation-free per harness rules)
// ---------------------------------------------------------------------------
__device__ __half g_qinfh[(size_t)BATCH * SEQ * DIM];  // query fp16 hi/lo
__device__ __half g_qinfl[(size_t)BATCH * SEQ * DIM];
__device__ __half g_Winfh[DIM * DIM];                  // W_in fp16 hi/lo
__device__ __half g_Winfl[DIM * DIM];
__device__ __half g_Wo16h[DIM * 2 * DIM];              // W_out fp16 hi
__device__ __half g_qfh [(size_t)BATCH * SEQ * DIM];   // q fp16 hi/lo
__device__ __half g_qfl [(size_t)BATCH * SEQ * DIM];
__device__ __half g_qT16h[(size_t)BATCH * DIM * SEQ];  // q^T fp16 hi (mix B)
__device__ __half g_Wfh [(size_t)BATCH * SEQ * SEQ];   // softmax weights fp16 hi
__device__ __half g_mixfh[(size_t)BATCH * SEQ * DIM];  // mix fp16 hi
__device__ float  g_S   [(size_t)BATCH * SEQ * SEQ];   // fp32 scores

// ---------------------------------------------------------------------------
// PTX helpers (portable: ldmatrix / mma.sync / cp.async)
// ---------------------------------------------------------------------------
__device__ __forceinline__ uint32_t smem_u32(const void* p) {
    uint32_t a;
    asm("{ .reg .u64 t; cvta.to.shared.u64 t, %1; cvt.u32.u64 %0, t; }" : "=r"(a) : "l"(p));
    return a;
}
__device__ __forceinline__ void ldsm4(uint32_t* r, uint32_t addr) {
    asm volatile("ldmatrix.sync.aligned.m8n8.x4.shared.b16 {%0,%1,%2,%3}, [%4];"
                 : "=r"(r[0]), "=r"(r[1]), "=r"(r[2]), "=r"(r[3]) : "r"(addr));
}
__device__ __forceinline__ void mma_f16(float* c, const uint32_t* a, const uint32_t* b) {
    asm volatile(
        "mma.sync.aligned.m16n8k16.row.col.f32.f16.f16.f32 "
        "{%0,%1,%2,%3}, {%4,%5,%6,%7}, {%8,%9}, {%0,%1,%2,%3};"
        : "+f"(c[0]), "+f"(c[1]), "+f"(c[2]), "+f"(c[3])
        : "r"(a[0]), "r"(a[1]), "r"(a[2]), "r"(a[3]), "r"(b[0]), "r"(b[1]));
}
#define CP16(s, g)  asm volatile("cp.async.cg.shared.global [%0], [%1], 16;" :: "r"(s), "l"(g) : "memory")
#define CP_COMMIT() asm volatile("cp.async.commit_group;" ::: "memory")
#define CP_WAIT0()  asm volatile("cp.async.wait_group 0;" ::: "memory")

__device__ __forceinline__ void split1h(float v, __half& h, __half& l) {
    h = __float2half_rn(v);
    l = __float2half_rn(v - __half2float(h));
}
__device__ __forceinline__ uint32_t pack2h(__half a, __half b) {
    return ((uint32_t)__half_as_ushort(b) << 16) | __half_as_ushort(a);
}

// ---------------------------------------------------------------------------
// GEMM: C[128x128] = A @ B^T, fp32 accum, fp16 m16n8k16 mma.
// PASSES=3: ah*bh + ah*bl + al*bh  (qproj — q errors enter scores twice)
// PASSES=2: ah*bh + ah*bl          (scores — calibrated error budget ok)
// PASSES=1: ah*bh                  (mix, out — post-softmax)
// Operands K-major fp16. K = nk*32. CONCAT: chunks>=16 read A1 (lda 512).
// EPI: 0 -> fp32 C; 1 -> fp16 hi/lo (Ch, Cl); 2 -> fp16 hi only (Ch).
// 256 threads = 8 warps (4m x 2n), warp tile 32x64, 2-stage cp.async,
// one __syncthreads per chunk, 2 CTA/SM. Acc indices compile-time constant.
// ---------------------------------------------------------------------------
#define LDS 40  // 16-bit elems per smem row (80B; conflict-free ldmatrix)
#define STG_BYTES (4 * 128 * LDS * 2)  // one stage: Ah,Al,Bh,Bl regions

template<int CONCAT, int EPI, int PASSES>
__device__ __forceinline__ void gemm_core(
    const __half* __restrict__ Ah, const __half* __restrict__ Al,
    const __half* __restrict__ A1h, long lda,
    const __half* __restrict__ Bh, const __half* __restrict__ Bl, long ldb,
    int nk,
    float* __restrict__ C, __half* __restrict__ Ch, __half* __restrict__ Cl,
    long ldc, int m0, int n0)
{
    extern __shared__ __half sm[];
    const uint32_t uS = smem_u32(sm);

    const int tid = threadIdx.x;
    const int wid = tid >> 5, lane = tid & 31;
    const int wm = wid >> 1, wn = wid & 1;
    const int kkx = wid & 1;
    const int r = tid >> 1, h16 = (tid & 1) << 4;

    const uint32_t rowoff = ((uint32_t)r * LDS + h16) * 2;

    auto issue = [&](int kc, int st) {
        const __half* a_h;
        if (CONCAT && kc >= 16)
            a_h = A1h + (size_t)(m0 + r) * 512 + (size_t)(kc - 16) * 32 + h16;
        else
            a_h = Ah + (size_t)(m0 + r) * lda + (size_t)kc * 32 + h16;
        const __half* b_h = Bh + (size_t)(n0 + r) * ldb + (size_t)kc * 32 + h16;
        const uint32_t base = uS + (uint32_t)st * STG_BYTES + rowoff;
        CP16(base + 0 * 128 * LDS * 2,      a_h);
        CP16(base + 0 * 128 * LDS * 2 + 16, a_h + 8);
        CP16(base + 2 * 128 * LDS * 2,      b_h);
        CP16(base + 2 * 128 * LDS * 2 + 16, b_h + 8);
        if (PASSES >= 2) {
            const __half* b_l = Bl + (size_t)(n0 + r) * ldb + (size_t)kc * 32 + h16;
            CP16(base + 3 * 128 * LDS * 2,      b_l);
            CP16(base + 3 * 128 * LDS * 2 + 16, b_l + 8);
        }
        if (PASSES == 3) {
            const __half* a_l = Al + (size_t)(m0 + r) * lda + (size_t)kc * 32 + h16;
            CP16(base + 1 * 128 * LDS * 2,      a_l);
            CP16(base + 1 * 128 * LDS * 2 + 16, a_l + 8);
        }
    };

    float acc[2][8][4] = {};

    issue(0, 0);
    CP_COMMIT();

    for (int kc = 0; kc < nk; ++kc) {
        const int st = kc & 1;
        CP_WAIT0();
        __syncthreads();
        if (kc + 1 < nk) { issue(kc + 1, st ^ 1); CP_COMMIT(); }

        const uint32_t sA  = uS + (uint32_t)st * STG_BYTES;
        const uint32_t sAl_ = sA + 128 * LDS * 2;
        const uint32_t sB  = sA + 2 * 128 * LDS * 2;
        const uint32_t sBl_ = sA + 3 * 128 * LDS * 2;

#pragma unroll
        for (int kk2 = 0; kk2 < 2; ++kk2) {
            const int kk = kk2 ^ kkx;   // address-level stagger only
            const uint32_t aoff =
                ((uint32_t)(wm * 32 + (lane & 15)) * LDS + kk * 16 + ((lane & 16) ? 8 : 0)) * 2;
            uint32_t ah[2][4], al[2][4];
            ldsm4(ah[0], sA + aoff);
            ldsm4(ah[1], sA + aoff + 16 * LDS * 2);
            if (PASSES == 3) {
                ldsm4(al[0], sAl_ + aoff);
                ldsm4(al[1], sAl_ + aoff + 16 * LDS * 2);
            }

            const uint32_t boff =
                ((uint32_t)(wn * 64 + (lane & 7) + ((lane & 16) ? 8 : 0)) * LDS
                 + kk * 16 + ((lane & 8) ? 8 : 0)) * 2;

#pragma unroll
            for (int jh = 0; jh < 2; ++jh) {
                uint32_t bh[4][2], bl[4][2];
#pragma unroll
                for (int jj = 0; jj < 2; ++jj) {
                    uint32_t tb[4];
                    const uint32_t bo = boff + (jh * 2 + jj) * 16 * LDS * 2;
                    ldsm4(tb, sB + bo);
                    bh[2 * jj][0] = tb[0]; bh[2 * jj][1] = tb[1];
                    bh[2 * jj + 1][0] = tb[2]; bh[2 * jj + 1][1] = tb[3];
                    if (PASSES >= 2) {
                        uint32_t tl[4];
                        ldsm4(tl, sBl_ + bo);
                        bl[2 * jj][0] = tl[0]; bl[2 * jj][1] = tl[1];
                        bl[2 * jj + 1][0] = tl[2]; bl[2 * jj + 1][1] = tl[3];
                    }
                }
#pragma unroll
                for (int im = 0; im < 2; ++im)
#pragma unroll
                    for (int j = 0; j < 4; ++j)
                        mma_f16(acc[im][jh * 4 + j], ah[im], bh[j]);
                if (PASSES >= 2) {
#pragma unroll
                    for (int im = 0; im < 2; ++im)
#pragma unroll
                        for (int j = 0; j < 4; ++j)
                            mma_f16(acc[im][jh * 4 + j], ah[im], bl[j]);
                }
                if (PASSES == 3) {
#pragma unroll
                    for (int im = 0; im < 2; ++im)
#pragma unroll
                        for (int j = 0; j < 4; ++j)
                            mma_f16(acc[im][jh * 4 + j], al[im], bh[j]);
                }
            }
        }
    }

    // epilogue
    const int g = lane >> 2, tg = lane & 3;
#pragma unroll
    for (int im = 0; im < 2; ++im) {
        const size_t row = (size_t)(m0 + wm * 32 + im * 16 + g);
#pragma unroll
        for (int j = 0; j < 8; ++j) {
            const size_t col = (size_t)(n0 + wn * 64 + j * 8 + tg * 2);
#pragma unroll
            for (int p = 0; p < 2; ++p) {
                const size_t rr = (row + p * 8) * ldc + col;
                const float v0 = acc[im][j][2 * p], v1 = acc[im][j][2 * p + 1];
                if (EPI == 0) {
                    *(float2*)(C + rr) = make_float2(v0, v1);
                } else if (EPI == 1) {
                    __half h0, l0, h1, l1;
                    split1h(v0, h0, l0);
                    split1h(v1, h1, l1);
                    *(uint32_t*)(Ch + rr) = pack2h(h0, h1);
                    *(uint32_t*)(Cl + rr) = pack2h(l0, l1);
                } else {
                    *(uint32_t*)(Ch + rr) = pack2h(__float2half_rn(v0), __float2half_rn(v1));
                }
            }
        }
    }
}

// ---------------------------------------------------------------------------
// GEMM kernels
// ---------------------------------------------------------------------------
__global__ void __launch_bounds__(256, 2) k_qproj() {
    gemm_core<0, 1, 3>(g_qinfh, g_qinfl, nullptr, DIM,
                       g_Winfh, g_Winfl, DIM, 16,
                       nullptr, g_qfh, g_qfl,
                       DIM, blockIdx.y * 128, blockIdx.x * 128);
}
__global__ void __launch_bounds__(256, 2) k_scores() {
    if (blockIdx.x > blockIdx.y) return;   // fully masked causal tile
    const size_t qo = (size_t)blockIdx.z * SEQ * DIM;
    gemm_core<0, 0, 2>(g_qfh + qo, nullptr, nullptr, DIM,
                       g_qfh + qo, g_qfl + qo, DIM, 16,
                       g_S + (size_t)blockIdx.z * SEQ * SEQ, nullptr, nullptr,
                       SEQ, blockIdx.y * 128, blockIdx.x * 128);
}
__global__ void __launch_bounds__(256, 2) k_mix() {
    // Longest-K tiles first for the work-steal tail.
    const int b = blockIdx.z;
    const int ry = (SEQ / 128 - 1) - blockIdx.y;
    const int m0 = ry * 128, n0 = blockIdx.x * 128;
    const size_t wo = (size_t)b * SEQ * SEQ, qo = (size_t)b * DIM * SEQ;
    const size_t mo = (size_t)b * SEQ * DIM;
    gemm_core<0, 2, 1>(g_Wfh + wo, nullptr, nullptr, SEQ,
                       g_qT16h + qo, nullptr, SEQ,
                       m0 / 32 + 4,
                       nullptr, g_mixfh + mo, nullptr,
                       DIM, m0, n0);
}
__global__ void __launch_bounds__(256, 2) k_out(float* __restrict__ out) {
    gemm_core<1, 0, 1>(g_mixfh, nullptr, g_qfh, DIM,
                       g_Wo16h, nullptr, 2 * DIM, 32,
                       out, nullptr, nullptr,
                       DIM, blockIdx.y * 128, blockIdx.x * 128);
}

// ---------------------------------------------------------------------------
// fp32 -> fp16 hi/lo split (query, W_in)
// ---------------------------------------------------------------------------
__global__ void __launch_bounds__(256) k_cvt(const float* __restrict__ src,
                                             __half* __restrict__ dh,
                                             __half* __restrict__ dl, size_t n) {
    size_t i = ((size_t)blockIdx.x * 256 + threadIdx.x) * 4;
    if (i >= n) return;
    float4 v = *(const float4*)(src + i);
    __half h[4], l[4];
    split1h(v.x, h[0], l[0]); split1h(v.y, h[1], l[1]);
    split1h(v.z, h[2], l[2]); split1h(v.w, h[3], l[3]);
    *(uint2*)(dh + i) = make_uint2(pack2h(h[0], h[1]), pack2h(h[2], h[3]));
    *(uint2*)(dl + i) = make_uint2(pack2h(l[0], l[1]), pack2h(l[2], l[3]));
}

// fp32 -> fp16 hi (W_out)
__global__ void __launch_bounds__(256) k_cvt16(const float* __restrict__ src,
                                               __half* __restrict__ dh, size_t n) {
    size_t i = ((size_t)blockIdx.x * 256 + threadIdx.x) * 4;
    if (i >= n) return;
    float4 v = *(const float4*)(src + i);
    *(uint2*)(dh + i) = make_uint2(
        pack2h(__float2half_rn(v.x), __float2half_rn(v.y)),
        pack2h(__float2half_rn(v.z), __float2half_rn(v.w)));
}

// ---------------------------------------------------------------------------
// Transpose: qT16[b][d][n] = qfh[b][n][d]  (fp16 copy-transpose)
// ---------------------------------------------------------------------------
__global__ void __launch_bounds__(256) k_transpose() {
    __shared__ __half t[32][33];
    const int b = blockIdx.z, n0 = blockIdx.x * 32, d0 = blockIdx.y * 32;
    const int tx = threadIdx.x & 31, ty = threadIdx.x >> 5;
    const size_t so = (size_t)b * SEQ * DIM, to = (size_t)b * DIM * SEQ;
#pragma unroll
    for (int j = 0; j < 4; ++j)
        t[ty + 8 * j][tx] = g_qfh[so + (size_t)(n0 + ty + 8 * j) * DIM + d0 + tx];
    __syncthreads();
#pragma unroll
    for (int j = 0; j < 4; ++j)
        g_qT16h[to + (size_t)(d0 + ty + 8 * j) * SEQ + n0 + tx] = t[tx][ty + 8 * j];
}

// ---------------------------------------------------------------------------
// Softmax: row n over keys m < n (strict causal); emits fp16 weights (hi only).
// Thread t owns 8 contiguous elements; streaming loads (rows read once).
// Writes only up to the 128-aligned k_mix limit.
// ---------------------------------------------------------------------------
__global__ void __launch_bounds__(256) k_softmax() {
    const int n = blockIdx.x, b = blockIdx.y;
    const size_t ro = ((size_t)b * SEQ + n) * SEQ;
    const float* row = g_S + ro;
    __half* wh = g_Wfh + ro;
    const int tid = threadIdx.x;
    const int mb = tid * 8;
    const int lim = (n / 128) * 128 + 128;
    __shared__ float red[8];

    float f[8];
    if (n > 0 && mb < n) {
        float4 v0 = __ldcs((const float4*)(row + mb));
        float4 v1 = __ldcs((const float4*)(row + mb + 4));
        f[0] = v0.x; f[1] = v0.y; f[2] = v0.z; f[3] = v0.w;
        f[4] = v1.x; f[5] = v1.y; f[6] = v1.z; f[7] = v1.w;
#pragma unroll
        for (int i = 0; i < 8; ++i)
            if (mb + i >= n) f[i] = -3.0e38f;
    } else {
#pragma unroll
        for (int i = 0; i < 8; ++i) f[i] = -3.0e38f;
    }

    if (n > 0) {
        float mx = -3.0e38f;
#pragma unroll
        for (int i = 0; i < 8; ++i) mx = fmaxf(mx, f[i]);
#pragma unroll
        for (int o = 16; o > 0; o >>= 1) mx = fmaxf(mx, __shfl_xor_sync(0xffffffffu, mx, o));
        if ((tid & 31) == 0) red[tid >> 5] = mx;
        __syncthreads();
        float bmx = red[0];
#pragma unroll
        for (int w = 1; w < 8; ++w) bmx = fmaxf(bmx, red[w]);
        __syncthreads();
        float s = 0.f;
#pragma unroll
        for (int i = 0; i < 8; ++i) {
            f[i] = (mb + i < n) ? __expf(f[i] - bmx) : 0.f;
            s += f[i];
        }
#pragma unroll
        for (int o = 16; o > 0; o >>= 1) s += __shfl_xor_sync(0xffffffffu, s, o);
        if ((tid & 31) == 0) red[tid >> 5] = s;
        __syncthreads();
        float tot = 0.f;
#pragma unroll
        for (int w = 0; w < 8; ++w) tot += red[w];
        const float inv = 1.f / tot;
#pragma unroll
        for (int i = 0; i < 8; ++i) f[i] *= inv;
    } else {
#pragma unroll
        for (int i = 0; i < 8; ++i) f[i] = 0.f;
    }

    if (mb < lim) {
        __half h[8];
#pragma unroll
        for (int i = 0; i < 8; ++i) h[i] = __float2half_rn(f[i]);
        *(uint4*)(wh + mb) = make_uint4(pack2h(h[0], h[1]), pack2h(h[2], h[3]),
                                        pack2h(h[4], h[5]), pack2h(h[6], h[7]));
    }
}

// ---------------------------------------------------------------------------
extern "C" void kernel_launch(void* const* d_in, const int* in_sizes, int n_in,
                              void* d_out, int out_size) {
    const float* query = (const float*)d_in[0];   // [16, 2048, 512]
    const float* W_in  = (const float*)d_in[1];   // [512, 512]
    const float* W_out = (const float*)d_in[2];   // [512, 1024]
    float* out = (float*)d_out;                   // [16, 2048, 512]

    const int smem = 2 * STG_BYTES;  // 81920
    static int init = 0;
    if (!init) {
        cudaFuncSetAttribute(k_qproj,  cudaFuncAttributeMaxDynamicSharedMemorySize, smem);
        cudaFuncSetAttribute(k_scores, cudaFuncAttributeMaxDynamicSharedMemorySize, smem);
        cudaFuncSetAttribute(k_mix,    cudaFuncAttributeMaxDynamicSharedMemorySize, smem);
        cudaFuncSetAttribute(k_out,    cudaFuncAttributeMaxDynamicSharedMemorySize, smem);
        init = 1;
    }

    __half *qinfh, *qinfl, *winfh, *winfl, *wo16h;
    cudaGetSymbolAddress((void**)&qinfh, g_qinfh);
    cudaGetSymbolAddress((void**)&qinfl, g_qinfl);
    cudaGetSymbolAddress((void**)&winfh, g_Winfh);
    cudaGetSymbolAddress((void**)&winfl, g_Winfl);
    cudaGetSymbolAddress((void**)&wo16h, g_Wo16h);

    const size_t nq = (size_t)BATCH * SEQ * DIM;
    k_cvt  <<<(unsigned)((nq / 4 + 255) / 256), 256>>>(query, qinfh, qinfl, nq);
    k_cvt  <<<(DIM * DIM / 4 + 255) / 256, 256>>>(W_in, winfh, winfl, DIM * DIM);
    k_cvt16<<<(DIM * 2 * DIM / 4 + 255) / 256, 256>>>(W_out, wo16h, DIM * 2 * DIM);

    k_qproj    <<<dim3(DIM / 128, (BATCH * SEQ) / 128), 256, smem>>>();
    k_transpose<<<dim3(SEQ / 32, DIM / 32, BATCH),      256>>>();
    k_scores   <<<dim3(SEQ / 128, SEQ / 128, BATCH),    256, smem>>>();
    k_softmax  <<<dim3(SEQ, BATCH),                     256>>>();
    k_mix      <<<dim3(DIM / 128, SEQ / 128, BATCH),    256, smem>>>();
    k_out      <<<dim3(DIM / 128, (BATCH * SEQ) / 128), 256, smem>>>(out);
}